// round 1
// baseline (speedup 1.0000x reference)
#include <cuda_runtime.h>
#include <math.h>

#define BSZ 4
#define TT 2048
#define CC 2048
#define NH 16
#define HD 128
#define MM (BSZ*TT)   // 8192

// ---------------- scratch (device globals: no allocation allowed) -------------
__device__ float g_q[(size_t)BSZ*NH*TT*HD];
__device__ float g_k[(size_t)BSZ*NH*TT*HD];
__device__ float g_v[(size_t)BSZ*NH*TT*HD];
__device__ float g_y[(size_t)BSZ*TT*CC];
__device__ float g_cos[TT*(HD/2)];
__device__ float g_sin[TT*(HD/2)];

// ---------------- RoPE cos/sin table (matches fp32 reference math) ------------
__global__ void rope_table_kernel() {
    int idx = blockIdx.x * blockDim.x + threadIdx.x;
    if (idx >= TT * (HD/2)) return;
    int t = idx / (HD/2);
    int i = idx % (HD/2);
    float inv = (float)pow(10000.0, -(double)(2*i) / (double)HD);
    float ang = (float)t * inv;
    g_cos[idx] = cosf(ang);
    g_sin[idx] = sinf(ang);
}

// ---------------- GEMM: out = A[M,K] @ W[N,K]^T -------------------------------
// MODE 0: plain row-major write out[m*CC + n]   (final projection)
// MODE 1: write to (B,H,T,hd) layout with RoPE  (Q, K)
// MODE 2: write to (B,H,T,hd) layout, no RoPE   (V)
template<int MODE>
__global__ __launch_bounds__(256)
void gemm128(const float* __restrict__ A, const float* __restrict__ W,
             float* __restrict__ out) {
    __shared__ float As[16][128];
    __shared__ float Bs[16][128];
    const int K = CC;
    int tid = threadIdx.x;
    int m0 = blockIdx.y << 7;
    int n0 = blockIdx.x << 7;
    int ty = tid >> 4, tx = tid & 15;
    int lrow = tid >> 2;           // 0..63
    int lc4  = (tid & 3) << 2;     // 0,4,8,12

    const float* Ap  = A + (size_t)(m0 + lrow) * K + lc4;
    const float* Ap2 = Ap + (size_t)64 * K;
    const float* Wpp = W + (size_t)(n0 + lrow) * K + lc4;
    const float* Wp2 = Wpp + (size_t)64 * K;

    float acc[8][8];
#pragma unroll
    for (int i = 0; i < 8; i++)
#pragma unroll
        for (int j = 0; j < 8; j++) acc[i][j] = 0.f;

    for (int k0 = 0; k0 < K; k0 += 16) {
        float4 a0 = *(const float4*)(Ap  + k0);
        float4 a1 = *(const float4*)(Ap2 + k0);
        float4 b0 = *(const float4*)(Wpp + k0);
        float4 b1 = *(const float4*)(Wp2 + k0);
        __syncthreads();
        As[lc4+0][lrow] = a0.x; As[lc4+1][lrow] = a0.y;
        As[lc4+2][lrow] = a0.z; As[lc4+3][lrow] = a0.w;
        As[lc4+0][lrow+64] = a1.x; As[lc4+1][lrow+64] = a1.y;
        As[lc4+2][lrow+64] = a1.z; As[lc4+3][lrow+64] = a1.w;
        Bs[lc4+0][lrow] = b0.x; Bs[lc4+1][lrow] = b0.y;
        Bs[lc4+2][lrow] = b0.z; Bs[lc4+3][lrow] = b0.w;
        Bs[lc4+0][lrow+64] = b1.x; Bs[lc4+1][lrow+64] = b1.y;
        Bs[lc4+2][lrow+64] = b1.z; Bs[lc4+3][lrow+64] = b1.w;
        __syncthreads();
#pragma unroll
        for (int kk = 0; kk < 16; kk++) {
            float ar[8], br[8];
            *(float4*)(ar)     = *(const float4*)&As[kk][ty << 2];
            *(float4*)(ar + 4) = *(const float4*)&As[kk][64 + (ty << 2)];
            *(float4*)(br)     = *(const float4*)&Bs[kk][tx << 2];
            *(float4*)(br + 4) = *(const float4*)&Bs[kk][64 + (tx << 2)];
#pragma unroll
            for (int i = 0; i < 8; i++)
#pragma unroll
                for (int j = 0; j < 8; j++)
                    acc[i][j] = fmaf(ar[i], br[j], acc[i][j]);
        }
    }

#pragma unroll
    for (int i = 0; i < 8; i++) {
        int m = m0 + ((i < 4) ? ((ty << 2) + i) : (64 + (ty << 2) + i - 4));
        if (MODE == 0) {
#pragma unroll
            for (int j = 0; j < 8; j++) {
                int n = n0 + ((j < 4) ? ((tx << 2) + j) : (64 + (tx << 2) + j - 4));
                out[(size_t)m * CC + n] = acc[i][j];
            }
        } else {
            int b = m >> 11;          // m / TT
            int t = m & (TT - 1);
#pragma unroll
            for (int j = 0; j < 8; j += 2) {
                int n = n0 + ((j < 4) ? ((tx << 2) + j) : (64 + (tx << 2) + j - 4));
                int h = n >> 7;
                int d = n & (HD - 1);
                size_t dst = ((size_t)(b * NH + h) * TT + t) * HD + d;
                float e = acc[i][j], o = acc[i][j + 1];
                if (MODE == 1) {
                    float cv = g_cos[t * (HD/2) + (d >> 1)];
                    float sv = g_sin[t * (HD/2) + (d >> 1)];
                    out[dst]     = e * cv - o * sv;
                    out[dst + 1] = o * cv + e * sv;
                } else {
                    out[dst] = e;
                    out[dst + 1] = o;
                }
            }
        }
    }
}

// ---------------- Flash attention (fp32, causal) -------------------------------
#define ABM 64
#define QLD 132   // 128 + 4 pad: float4-aligned, conflict-free for col = tx+16c
#define PLD 68    // 64 + 4 pad
#define SMEM_ATTN ((ABM*QLD*2 + ABM*PLD) * 4)

__global__ __launch_bounds__(256, 2)
void attn_kernel() {
    extern __shared__ float sm[];
    float* Qs = sm;                    // [64][132]
    float* Ts = sm + ABM * QLD;        // [64][132] K then V (reused)
    float* Ps = sm + 2 * ABM * QLD;    // [64][68]

    int qtile = blockIdx.x;
    int bh    = blockIdx.y;            // b*NH + h
    int tid = threadIdx.x;
    int ty = tid >> 4, tx = tid & 15;
    const float scale = 0.08838834764831843f;  // 1/sqrt(128)

    const float* Qb = g_q + (size_t)bh * TT * HD + (size_t)qtile * ABM * HD;
    const float* Kb = g_k + (size_t)bh * TT * HD;
    const float* Vb = g_v + (size_t)bh * TT * HD;

    // load + prescale Q tile
    for (int i = tid; i < ABM * 32; i += 256) {
        int row = i >> 5, c4 = (i & 31) << 2;
        float4 v = *(const float4*)(Qb + row * HD + c4);
        float* d = &Qs[row * QLD + c4];
        d[0] = v.x * scale; d[1] = v.y * scale;
        d[2] = v.z * scale; d[3] = v.w * scale;
    }

    float o[4][8];
    float m_i[4], l_i[4];
#pragma unroll
    for (int r = 0; r < 4; r++) {
        m_i[r] = -1e30f; l_i[r] = 0.f;
#pragma unroll
        for (int c = 0; c < 8; c++) o[r][c] = 0.f;
    }

    int ntiles = qtile + 1;
    for (int j = 0; j < ntiles; j++) {
        __syncthreads();  // prior PV done reading Ts; Q load done (j==0)
        const float* Kt = Kb + (size_t)j * ABM * HD;
        for (int i = tid; i < ABM * 32; i += 256) {
            int row = i >> 5, c4 = (i & 31) << 2;
            *(float4*)&Ts[row * QLD + c4] = *(const float4*)(Kt + row * HD + c4);
        }
        __syncthreads();

        // S = Qs @ Ts^T   rows ty*4+r, cols tx+16*c
        float s[4][4];
#pragma unroll
        for (int r = 0; r < 4; r++)
#pragma unroll
            for (int c = 0; c < 4; c++) s[r][c] = 0.f;

#pragma unroll 2
        for (int kk = 0; kk < HD; kk += 4) {
            float4 qv[4], kv[4];
#pragma unroll
            for (int r = 0; r < 4; r++)
                qv[r] = *(const float4*)&Qs[((ty << 2) + r) * QLD + kk];
#pragma unroll
            for (int c = 0; c < 4; c++)
                kv[c] = *(const float4*)&Ts[(tx + (c << 4)) * QLD + kk];
#pragma unroll
            for (int r = 0; r < 4; r++)
#pragma unroll
                for (int c = 0; c < 4; c++) {
                    s[r][c] = fmaf(qv[r].x, kv[c].x, s[r][c]);
                    s[r][c] = fmaf(qv[r].y, kv[c].y, s[r][c]);
                    s[r][c] = fmaf(qv[r].z, kv[c].z, s[r][c]);
                    s[r][c] = fmaf(qv[r].w, kv[c].w, s[r][c]);
                }
        }

        if (j == qtile) {  // diagonal tile: causal mask
#pragma unroll
            for (int r = 0; r < 4; r++)
#pragma unroll
                for (int c = 0; c < 4; c++)
                    if (tx + (c << 4) > (ty << 2) + r) s[r][c] = -1e30f;
        }

        // online softmax update
#pragma unroll
        for (int r = 0; r < 4; r++) {
            float rm = fmaxf(fmaxf(s[r][0], s[r][1]), fmaxf(s[r][2], s[r][3]));
#pragma unroll
            for (int off = 1; off < 16; off <<= 1)
                rm = fmaxf(rm, __shfl_xor_sync(0xffffffffu, rm, off));
            float mn = fmaxf(m_i[r], rm);
            float alpha = __expf(m_i[r] - mn);
            float p[4], rs = 0.f;
#pragma unroll
            for (int c = 0; c < 4; c++) { p[c] = __expf(s[r][c] - mn); rs += p[c]; }
#pragma unroll
            for (int off = 1; off < 16; off <<= 1)
                rs += __shfl_xor_sync(0xffffffffu, rs, off);
            l_i[r] = l_i[r] * alpha + rs;
            m_i[r] = mn;
#pragma unroll
            for (int c = 0; c < 8; c++) o[r][c] *= alpha;
#pragma unroll
            for (int c = 0; c < 4; c++)
                Ps[((ty << 2) + r) * PLD + tx + (c << 4)] = p[c];
        }
        __syncthreads();  // Ps visible; K reads done

        // load V tile into Ts
        const float* Vt = Vb + (size_t)j * ABM * HD;
        for (int i = tid; i < ABM * 32; i += 256) {
            int row = i >> 5, c4 = (i & 31) << 2;
            *(float4*)&Ts[row * QLD + c4] = *(const float4*)(Vt + row * HD + c4);
        }
        __syncthreads();

        // O += P @ V   rows ty*4+r, cols tx+16*c (c=0..7)
#pragma unroll 2
        for (int kk = 0; kk < ABM; kk += 4) {
            float pvals[4][4];
#pragma unroll
            for (int r = 0; r < 4; r++) {
                float4 t4 = *(const float4*)&Ps[((ty << 2) + r) * PLD + kk];
                pvals[r][0] = t4.x; pvals[r][1] = t4.y;
                pvals[r][2] = t4.z; pvals[r][3] = t4.w;
            }
#pragma unroll
            for (int q = 0; q < 4; q++) {
                float vr[8];
#pragma unroll
                for (int c = 0; c < 8; c++)
                    vr[c] = Ts[(kk + q) * QLD + tx + (c << 4)];
#pragma unroll
                for (int r = 0; r < 4; r++)
#pragma unroll
                    for (int c = 0; c < 8; c++)
                        o[r][c] = fmaf(pvals[r][q], vr[c], o[r][c]);
            }
        }
    }

    // write y in (B,T,C) layout for final projection
    int b = bh >> 4, h = bh & 15;
#pragma unroll
    for (int r = 0; r < 4; r++) {
        int tq = qtile * ABM + (ty << 2) + r;
        float inv = 1.0f / l_i[r];
#pragma unroll
        for (int c = 0; c < 8; c++) {
            int d = tx + (c << 4);
            g_y[(size_t)(b * TT + tq) * CC + h * HD + d] = o[r][c] * inv;
        }
    }
}

// ---------------- launch --------------------------------------------------------
extern "C" void kernel_launch(void* const* d_in, const int* in_sizes, int n_in,
                              void* d_out, int out_size) {
    const float* x  = (const float*)d_in[0];
    const float* Wq = (const float*)d_in[1];
    const float* Wk = (const float*)d_in[2];
    const float* Wv = (const float*)d_in[3];
    const float* Wp = (const float*)d_in[4];
    float* out = (float*)d_out;

    float *qp, *kp, *vp, *yp;
    cudaGetSymbolAddress((void**)&qp, g_q);
    cudaGetSymbolAddress((void**)&kp, g_k);
    cudaGetSymbolAddress((void**)&vp, g_v);
    cudaGetSymbolAddress((void**)&yp, g_y);

    rope_table_kernel<<<(TT * (HD/2) + 255) / 256, 256>>>();

    dim3 gg(CC / 128, MM / 128);
    gemm128<1><<<gg, 256>>>(x, Wq, qp);
    gemm128<1><<<gg, 256>>>(x, Wk, kp);
    gemm128<2><<<gg, 256>>>(x, Wv, vp);

    cudaFuncSetAttribute(attn_kernel,
                         cudaFuncAttributeMaxDynamicSharedMemorySize, SMEM_ATTN);
    attn_kernel<<<dim3(TT / ABM, BSZ * NH), 256, SMEM_ATTN>>>();

    gemm128<0><<<gg, 256>>>(yp, Wp, out);
}

// round 3
// speedup vs baseline: 1.8870x; 1.8870x over previous
#include <cuda_runtime.h>
#include <cuda_bf16.h>
#include <math.h>
#include <cstdint>

#define BSZ 4
#define TT 2048
#define CC 2048
#define NH 16
#define HD 128
#define MM (BSZ*TT)   // 8192

// ---------------- scratch (device globals: no allocation allowed) -------------
__device__ float g_q[(size_t)BSZ*NH*TT*HD];
__device__ float g_k[(size_t)BSZ*NH*TT*HD];
__device__ float g_v[(size_t)BSZ*NH*TT*HD];
__device__ float g_y[(size_t)BSZ*TT*CC];
__device__ float g_cos[TT*(HD/2)];
__device__ float g_sin[TT*(HD/2)];
// split-bf16 operand buffers
__device__ __nv_bfloat16 g_xh[(size_t)MM*CC];
__device__ __nv_bfloat16 g_xl[(size_t)MM*CC];
__device__ __nv_bfloat16 g_yh[(size_t)MM*CC];
__device__ __nv_bfloat16 g_yl[(size_t)MM*CC];
__device__ __nv_bfloat16 g_wh[4][(size_t)CC*CC];
__device__ __nv_bfloat16 g_wl[4][(size_t)CC*CC];

// ---------------- PTX helpers --------------------------------------------------
__device__ __forceinline__ uint32_t smem_u32(const void* p) {
    uint32_t a;
    asm("{ .reg .u64 t; cvta.to.shared.u64 t, %1; cvt.u32.u64 %0, t; }" : "=r"(a) : "l"(p));
    return a;
}
#define CP16(dst, src)  asm volatile("cp.async.cg.shared.global [%0], [%1], 16;" :: "r"(dst), "l"(src) : "memory")
#define CP_COMMIT()     asm volatile("cp.async.commit_group;" ::: "memory")
#define CP_WAIT(n)      asm volatile("cp.async.wait_group %0;" :: "n"(n) : "memory")

__device__ __forceinline__ void ldmx4(uint32_t* r, uint32_t addr) {
    asm volatile("ldmatrix.sync.aligned.m8n8.x4.shared.b16 {%0,%1,%2,%3}, [%4];"
                 : "=r"(r[0]), "=r"(r[1]), "=r"(r[2]), "=r"(r[3]) : "r"(addr));
}
__device__ __forceinline__ void mma16816(float* d, const uint32_t* a,
                                         uint32_t b0, uint32_t b1) {
    asm volatile("mma.sync.aligned.m16n8k16.row.col.f32.bf16.bf16.f32 "
                 "{%0,%1,%2,%3}, {%4,%5,%6,%7}, {%8,%9}, {%0,%1,%2,%3};"
                 : "+f"(d[0]), "+f"(d[1]), "+f"(d[2]), "+f"(d[3])
                 : "r"(a[0]), "r"(a[1]), "r"(a[2]), "r"(a[3]), "r"(b0), "r"(b1));
}

// ---------------- RoPE cos/sin table -------------------------------------------
__global__ void rope_table_kernel() {
    int idx = blockIdx.x * blockDim.x + threadIdx.x;
    if (idx >= TT * (HD/2)) return;
    int t = idx / (HD/2);
    int i = idx % (HD/2);
    float inv = (float)pow(10000.0, -(double)(2*i) / (double)HD);
    float ang = (float)t * inv;
    g_cos[idx] = cosf(ang);
    g_sin[idx] = sinf(ang);
}

// ---------------- fp32 -> (bf16 hi, bf16 lo) split ------------------------------
__global__ void cvt_split_kernel(const float* __restrict__ in,
                                 __nv_bfloat16* __restrict__ hi,
                                 __nv_bfloat16* __restrict__ lo, int n4) {
    int i = blockIdx.x * blockDim.x + threadIdx.x;
    if (i >= n4) return;
    float4 v = ((const float4*)in)[i];
    __nv_bfloat16 h0 = __float2bfloat16(v.x), h1 = __float2bfloat16(v.y);
    __nv_bfloat16 h2 = __float2bfloat16(v.z), h3 = __float2bfloat16(v.w);
    __nv_bfloat16 l0 = __float2bfloat16(v.x - __bfloat162float(h0));
    __nv_bfloat16 l1 = __float2bfloat16(v.y - __bfloat162float(h1));
    __nv_bfloat16 l2 = __float2bfloat16(v.z - __bfloat162float(h2));
    __nv_bfloat16 l3 = __float2bfloat16(v.w - __bfloat162float(h3));
    __nv_bfloat162 hp0(h0, h1), hp1(h2, h3), lp0(l0, l1), lp1(l2, l3);
    ((__nv_bfloat162*)hi)[i*2]   = hp0;
    ((__nv_bfloat162*)hi)[i*2+1] = hp1;
    ((__nv_bfloat162*)lo)[i*2]   = lp0;
    ((__nv_bfloat162*)lo)[i*2+1] = lp1;
}

// ---------------- split-bf16 GEMM via mma.sync: out = A[M,K] @ W[N,K]^T ---------
// CTA 128x256, BK=64, 2-stage cp.async, 8 warps (2m x 4n), warp tile 64x64.
// MODE 0: row-major out; MODE 1: (B,H,T,hd)+RoPE; MODE 2: (B,H,T,hd)
#define BM 128
#define BN 256
#define BK 64
#define NKIT (CC / BK)     // 32
#define AH_OFF 0
#define AL_OFF 16384
#define BH_OFF 32768
#define BL_OFF 65536
#define STG_SZ 98304
#define GEMM_SMEM (1024 + 2*STG_SZ)

// swizzled byte offset within a [rows][128B] k-major tile
__device__ __forceinline__ uint32_t swzoff(int r, int chunk) {
    return (uint32_t)(r * 128 + ((chunk ^ (r & 7)) << 4));
}

template<int MODE>
__global__ __launch_bounds__(256, 1)
void gemm_mma(const __nv_bfloat16* __restrict__ Ah, const __nv_bfloat16* __restrict__ Al,
              const __nv_bfloat16* __restrict__ Bh, const __nv_bfloat16* __restrict__ Bl,
              float* __restrict__ out) {
    extern __shared__ char smraw[];
    const uint32_t raw = smem_u32(smraw);
    const uint32_t ab = (raw + 1023) & ~1023u;
    const int tid = threadIdx.x;
    const int wid = tid >> 5, lane = tid & 31;
    const int wm = wid & 1;        // 0..1  (64 rows)
    const int wn = wid >> 1;       // 0..3  (64 cols)
    const size_t m0 = (size_t)blockIdx.y * BM;
    const size_t n0 = (size_t)blockIdx.x * BN;
    const int K = CC;

    auto load_stage = [&](int s, int k0) {
        uint32_t sb = ab + s * STG_SZ;
#pragma unroll
        for (int v = 0; v < 8; v++) {          // A: 2048 ops / 256 thr
            int i = v * 256 + tid;
            int t = i >> 10;
            int r = (i >> 3) & 127;
            int c = i & 7;
            const __nv_bfloat16* src = (t ? Al : Ah) + (m0 + r) * (size_t)K + k0 + c * 8;
            CP16(sb + (t ? AL_OFF : AH_OFF) + swzoff(r, c), src);
        }
#pragma unroll
        for (int v = 0; v < 16; v++) {         // B: 4096 ops
            int i = v * 256 + tid;
            int t = i >> 11;
            int r = (i >> 3) & 255;
            int c = i & 7;
            const __nv_bfloat16* src = (t ? Bl : Bh) + (n0 + r) * (size_t)K + k0 + c * 8;
            CP16(sb + (t ? BL_OFF : BH_OFF) + swzoff(r, c), src);
        }
    };

    float acc[4][8][4];
#pragma unroll
    for (int i = 0; i < 4; i++)
#pragma unroll
        for (int j = 0; j < 8; j++)
#pragma unroll
            for (int q = 0; q < 4; q++) acc[i][j][q] = 0.f;

    // precompute ldmatrix lane rows
    const int a_row = wm * 64 + (lane & 15);            // + f*16
    const int a_csel = lane >> 4;                        // chunk low bit
    const int b_row = wn * 64 + ((lane >> 4) << 3) + (lane & 7);  // + p*16
    const int b_csel = (lane >> 3) & 1;

    load_stage(0, 0);
    CP_COMMIT();

    for (int c = 0; c < NKIT; ++c) {
        if (c + 1 < NKIT) {
            load_stage((c + 1) & 1, (c + 1) * BK);
            CP_COMMIT();
            CP_WAIT(1);
        } else {
            CP_WAIT(0);
        }
        __syncthreads();

        uint32_t sb = ab + (c & 1) * STG_SZ;
#pragma unroll
        for (int ks = 0; ks < 4; ks++) {
            uint32_t ah[4][4], al[4][4], bh[4][4], bl[4][4];
#pragma unroll
            for (int f = 0; f < 4; f++) {
                int r = a_row + f * 16;
                uint32_t off = swzoff(r, 2 * ks + a_csel);
                ldmx4(ah[f], sb + AH_OFF + off);
                ldmx4(al[f], sb + AL_OFF + off);
            }
#pragma unroll
            for (int p = 0; p < 4; p++) {
                int r = b_row + p * 16;
                uint32_t off = swzoff(r, 2 * ks + b_csel);
                ldmx4(bh[p], sb + BH_OFF + off);
                ldmx4(bl[p], sb + BL_OFF + off);
            }
#pragma unroll
            for (int mf = 0; mf < 4; mf++)
#pragma unroll
                for (int nf = 0; nf < 8; nf++) {
                    int p = nf >> 1;
                    int e = (nf & 1) << 1;   // 0 -> regs 0,1 ; 1 -> regs 2,3
                    mma16816(acc[mf][nf], ah[mf], bh[p][e], bh[p][e + 1]);
                    mma16816(acc[mf][nf], ah[mf], bl[p][e], bl[p][e + 1]);
                    mma16816(acc[mf][nf], al[mf], bh[p][e], bh[p][e + 1]);
                }
        }
        __syncthreads();
    }

    // ---- epilogue: direct stores (d0,d1 is an even/odd RoPE pair) ----
    const int tr = lane >> 2;
    const int tc = (lane & 3) << 1;
#pragma unroll
    for (int mf = 0; mf < 4; mf++) {
#pragma unroll
        for (int nf = 0; nf < 8; nf++) {
            int mA = (int)m0 + wm * 64 + mf * 16 + tr;
            int n  = (int)n0 + wn * 64 + nf * 8 + tc;
            float* d = acc[mf][nf];
#pragma unroll
            for (int half = 0; half < 2; half++) {
                int m = mA + half * 8;
                float e = d[half * 2], o = d[half * 2 + 1];
                if (MODE == 0) {
                    float2 v2 = {e, o};
                    *(float2*)(out + (size_t)m * CC + n) = v2;
                } else {
                    int b = m >> 11;
                    int t = m & (TT - 1);
                    int h = n >> 7;
                    int dd = n & (HD - 1);
                    size_t dst = ((size_t)(b * NH + h) * TT + t) * HD + dd;
                    if (MODE == 1) {
                        float cv = g_cos[t * (HD/2) + (dd >> 1)];
                        float sv = g_sin[t * (HD/2) + (dd >> 1)];
                        float2 v2 = {e * cv - o * sv, o * cv + e * sv};
                        *(float2*)(out + dst) = v2;
                    } else {
                        float2 v2 = {e, o};
                        *(float2*)(out + dst) = v2;
                    }
                }
            }
        }
    }
}

// ---------------- Flash attention (fp32, causal) -------------------------------
#define ABM 64
#define QLD 132
#define PLD 68
#define SMEM_ATTN ((ABM*QLD*2 + ABM*PLD) * 4)

__global__ __launch_bounds__(256, 2)
void attn_kernel() {
    extern __shared__ float smf[];
    float* Qs = smf;
    float* Ts = smf + ABM * QLD;
    float* Ps = smf + 2 * ABM * QLD;

    int qtile = blockIdx.x;
    int bh    = blockIdx.y;
    int tid = threadIdx.x;
    int ty = tid >> 4, tx = tid & 15;
    const float scale = 0.08838834764831843f;

    const float* Qb = g_q + (size_t)bh * TT * HD + (size_t)qtile * ABM * HD;
    const float* Kb = g_k + (size_t)bh * TT * HD;
    const float* Vb = g_v + (size_t)bh * TT * HD;

    for (int i = tid; i < ABM * 32; i += 256) {
        int row = i >> 5, c4 = (i & 31) << 2;
        float4 v = *(const float4*)(Qb + row * HD + c4);
        float* d = &Qs[row * QLD + c4];
        d[0] = v.x * scale; d[1] = v.y * scale;
        d[2] = v.z * scale; d[3] = v.w * scale;
    }

    float o[4][8];
    float m_i[4], l_i[4];
#pragma unroll
    for (int r = 0; r < 4; r++) {
        m_i[r] = -1e30f; l_i[r] = 0.f;
#pragma unroll
        for (int c = 0; c < 8; c++) o[r][c] = 0.f;
    }

    int ntiles = qtile + 1;
    for (int j = 0; j < ntiles; j++) {
        __syncthreads();
        const float* Kt = Kb + (size_t)j * ABM * HD;
        for (int i = tid; i < ABM * 32; i += 256) {
            int row = i >> 5, c4 = (i & 31) << 2;
            *(float4*)&Ts[row * QLD + c4] = *(const float4*)(Kt + row * HD + c4);
        }
        __syncthreads();

        float s[4][4];
#pragma unroll
        for (int r = 0; r < 4; r++)
#pragma unroll
            for (int c = 0; c < 4; c++) s[r][c] = 0.f;

#pragma unroll 2
        for (int kk = 0; kk < HD; kk += 4) {
            float4 qv[4], kv[4];
#pragma unroll
            for (int r = 0; r < 4; r++)
                qv[r] = *(const float4*)&Qs[((ty << 2) + r) * QLD + kk];
#pragma unroll
            for (int c = 0; c < 4; c++)
                kv[c] = *(const float4*)&Ts[(tx + (c << 4)) * QLD + kk];
#pragma unroll
            for (int r = 0; r < 4; r++)
#pragma unroll
                for (int c = 0; c < 4; c++) {
                    s[r][c] = fmaf(qv[r].x, kv[c].x, s[r][c]);
                    s[r][c] = fmaf(qv[r].y, kv[c].y, s[r][c]);
                    s[r][c] = fmaf(qv[r].z, kv[c].z, s[r][c]);
                    s[r][c] = fmaf(qv[r].w, kv[c].w, s[r][c]);
                }
        }

        if (j == qtile) {
#pragma unroll
            for (int r = 0; r < 4; r++)
#pragma unroll
                for (int c = 0; c < 4; c++)
                    if (tx + (c << 4) > (ty << 2) + r) s[r][c] = -1e30f;
        }

#pragma unroll
        for (int r = 0; r < 4; r++) {
            float rm = fmaxf(fmaxf(s[r][0], s[r][1]), fmaxf(s[r][2], s[r][3]));
#pragma unroll
            for (int off = 1; off < 16; off <<= 1)
                rm = fmaxf(rm, __shfl_xor_sync(0xffffffffu, rm, off));
            float mn = fmaxf(m_i[r], rm);
            float alpha = __expf(m_i[r] - mn);
            float p[4], rs = 0.f;
#pragma unroll
            for (int c = 0; c < 4; c++) { p[c] = __expf(s[r][c] - mn); rs += p[c]; }
#pragma unroll
            for (int off = 1; off < 16; off <<= 1)
                rs += __shfl_xor_sync(0xffffffffu, rs, off);
            l_i[r] = l_i[r] * alpha + rs;
            m_i[r] = mn;
#pragma unroll
            for (int c = 0; c < 8; c++) o[r][c] *= alpha;
#pragma unroll
            for (int c = 0; c < 4; c++)
                Ps[((ty << 2) + r) * PLD + tx + (c << 4)] = p[c];
        }
        __syncthreads();

        const float* Vt = Vb + (size_t)j * ABM * HD;
        for (int i = tid; i < ABM * 32; i += 256) {
            int row = i >> 5, c4 = (i & 31) << 2;
            *(float4*)&Ts[row * QLD + c4] = *(const float4*)(Vt + row * HD + c4);
        }
        __syncthreads();

#pragma unroll 2
        for (int kk = 0; kk < ABM; kk += 4) {
            float pvals[4][4];
#pragma unroll
            for (int r = 0; r < 4; r++) {
                float4 t4 = *(const float4*)&Ps[((ty << 2) + r) * PLD + kk];
                pvals[r][0] = t4.x; pvals[r][1] = t4.y;
                pvals[r][2] = t4.z; pvals[r][3] = t4.w;
            }
#pragma unroll
            for (int q = 0; q < 4; q++) {
                float vr[8];
#pragma unroll
                for (int c = 0; c < 8; c++)
                    vr[c] = Ts[(kk + q) * QLD + tx + (c << 4)];
#pragma unroll
                for (int r = 0; r < 4; r++)
#pragma unroll
                    for (int c = 0; c < 8; c++)
                        o[r][c] = fmaf(pvals[r][q], vr[c], o[r][c]);
            }
        }
    }

    int b = bh >> 4, h = bh & 15;
#pragma unroll
    for (int r = 0; r < 4; r++) {
        int tq = qtile * ABM + (ty << 2) + r;
        float inv = 1.0f / l_i[r];
#pragma unroll
        for (int c = 0; c < 8; c++) {
            int d = tx + (c << 4);
            g_y[(size_t)(b * TT + tq) * CC + h * HD + d] = o[r][c] * inv;
        }
    }
}

// ---------------- launch --------------------------------------------------------
extern "C" void kernel_launch(void* const* d_in, const int* in_sizes, int n_in,
                              void* d_out, int out_size) {
    const float* x  = (const float*)d_in[0];
    const float* Wq = (const float*)d_in[1];
    const float* Wk = (const float*)d_in[2];
    const float* Wv = (const float*)d_in[3];
    const float* Wp = (const float*)d_in[4];
    float* out = (float*)d_out;

    float *qp, *kp, *vp, *yp;
    cudaGetSymbolAddress((void**)&qp, g_q);
    cudaGetSymbolAddress((void**)&kp, g_k);
    cudaGetSymbolAddress((void**)&vp, g_v);
    cudaGetSymbolAddress((void**)&yp, g_y);
    __nv_bfloat16 *xh, *xl, *yh, *yl, *wh, *wl;
    cudaGetSymbolAddress((void**)&xh, g_xh);
    cudaGetSymbolAddress((void**)&xl, g_xl);
    cudaGetSymbolAddress((void**)&yh, g_yh);
    cudaGetSymbolAddress((void**)&yl, g_yl);
    cudaGetSymbolAddress((void**)&wh, g_wh);
    cudaGetSymbolAddress((void**)&wl, g_wl);

    rope_table_kernel<<<(TT * (HD/2) + 255) / 256, 256>>>();

    const int NX4 = MM * CC / 4;
    const int NW4 = CC * CC / 4;
    cvt_split_kernel<<<(NX4 + 255) / 256, 256>>>(x, xh, xl, NX4);
    const float* Ws[4] = {Wq, Wk, Wv, Wp};
    for (int i = 0; i < 4; i++)
        cvt_split_kernel<<<(NW4 + 255) / 256, 256>>>(Ws[i], wh + (size_t)i * CC * CC,
                                                     wl + (size_t)i * CC * CC, NW4);

    cudaFuncSetAttribute(gemm_mma<0>, cudaFuncAttributeMaxDynamicSharedMemorySize, GEMM_SMEM);
    cudaFuncSetAttribute(gemm_mma<1>, cudaFuncAttributeMaxDynamicSharedMemorySize, GEMM_SMEM);
    cudaFuncSetAttribute(gemm_mma<2>, cudaFuncAttributeMaxDynamicSharedMemorySize, GEMM_SMEM);

    dim3 gg(CC / BN, MM / BM);     // (8, 64)
    gemm_mma<1><<<gg, 256, GEMM_SMEM>>>(xh, xl, wh + (size_t)0 * CC * CC, wl + (size_t)0 * CC * CC, qp);
    gemm_mma<1><<<gg, 256, GEMM_SMEM>>>(xh, xl, wh + (size_t)1 * CC * CC, wl + (size_t)1 * CC * CC, kp);
    gemm_mma<2><<<gg, 256, GEMM_SMEM>>>(xh, xl, wh + (size_t)2 * CC * CC, wl + (size_t)2 * CC * CC, vp);

    cudaFuncSetAttribute(attn_kernel, cudaFuncAttributeMaxDynamicSharedMemorySize, SMEM_ATTN);
    attn_kernel<<<dim3(TT / ABM, BSZ * NH), 256, SMEM_ATTN>>>();

    cvt_split_kernel<<<(NX4 + 255) / 256, 256>>>(yp, yh, yl, NX4);
    gemm_mma<0><<<gg, 256, GEMM_SMEM>>>(yh, yl, wh + (size_t)3 * CC * CC, wl + (size_t)3 * CC * CC, out);
}

// round 4
// speedup vs baseline: 2.0283x; 1.0749x over previous
#include <cuda_runtime.h>
#include <cuda.h>
#include <cuda_bf16.h>
#include <math.h>
#include <cstdint>

#define BSZ 4
#define TT 2048
#define CC 2048
#define NH 16
#define HD 128
#define MM (BSZ*TT)   // 8192

// ---------------- scratch (device globals: no allocation allowed) -------------
__device__ float g_q[(size_t)BSZ*NH*TT*HD];
__device__ float g_k[(size_t)BSZ*NH*TT*HD];
__device__ float g_v[(size_t)BSZ*NH*TT*HD];
__device__ float g_y[(size_t)BSZ*TT*CC];
__device__ float g_cos[TT*(HD/2)];
__device__ float g_sin[TT*(HD/2)];
// split-bf16 operand buffers (1KB aligned for TMA)
__device__ __align__(1024) __nv_bfloat16 g_xh[(size_t)MM*CC];
__device__ __align__(1024) __nv_bfloat16 g_xl[(size_t)MM*CC];
__device__ __align__(1024) __nv_bfloat16 g_yh[(size_t)MM*CC];
__device__ __align__(1024) __nv_bfloat16 g_yl[(size_t)MM*CC];
__device__ __align__(1024) __nv_bfloat16 g_wh[4][(size_t)CC*CC];
__device__ __align__(1024) __nv_bfloat16 g_wl[4][(size_t)CC*CC];

// ---------------- PTX helpers --------------------------------------------------
__device__ __forceinline__ uint32_t smem_u32(const void* p) {
    uint32_t a;
    asm("{ .reg .u64 t; cvta.to.shared.u64 t, %1; cvt.u32.u64 %0, t; }" : "=r"(a) : "l"(p));
    return a;
}
#define MBAR_INIT(a, n) asm volatile("mbarrier.init.shared.b64 [%0], %1;" :: "r"(a), "r"(n) : "memory")
#define MBAR_ARRIVE(a)  asm volatile("mbarrier.arrive.shared.b64 _, [%0];" :: "r"(a) : "memory")
#define MBAR_EXPECT(a, tx) asm volatile("mbarrier.arrive.expect_tx.shared.b64 _, [%0], %1;" :: "r"(a), "r"(tx) : "memory")
#define MBAR_WAIT(a, ph) do {                                                      \
    uint32_t _m = (a), _p = (ph), _d;                                              \
    asm volatile("{\n\t.reg .pred p;\n\t"                                          \
        "mbarrier.try_wait.parity.acquire.cta.shared::cta.b64 p, [%1], %2;\n\t"    \
        "selp.b32 %0, 1, 0, p;\n\t}" : "=r"(_d) : "r"(_m), "r"(_p) : "memory");    \
    if (!_d) {                                                                     \
        asm volatile("{\n\t.reg .pred P1;\n\t"                                     \
            "WL_%=:\n\t"                                                           \
            "mbarrier.try_wait.parity.acquire.cta.shared::cta.b64 P1, [%0], %1, 0x989680;\n\t" \
            "@P1 bra.uni WD_%=;\n\tbra.uni WL_%=;\n\tWD_%=:\n\t}"                  \
            :: "r"(_m), "r"(_p) : "memory");                                       \
    }                                                                              \
} while (0)
#define TMA2D(dst, map, cx, cy, mb) \
    asm volatile("cp.async.bulk.tensor.2d.shared::cta.global.tile.mbarrier::complete_tx::bytes " \
        "[%0], [%1, {%2, %3}], [%4];" \
        :: "r"(dst), "l"(map), "r"(cx), "r"(cy), "r"(mb) : "memory")

__device__ __forceinline__ void ldmx4(uint32_t* r, uint32_t addr) {
    asm volatile("ldmatrix.sync.aligned.m8n8.x4.shared.b16 {%0,%1,%2,%3}, [%4];"
                 : "=r"(r[0]), "=r"(r[1]), "=r"(r[2]), "=r"(r[3]) : "r"(addr));
}
__device__ __forceinline__ void mma16816(float* d, const uint32_t* a,
                                         uint32_t b0, uint32_t b1) {
    asm volatile("mma.sync.aligned.m16n8k16.row.col.f32.bf16.bf16.f32 "
                 "{%0,%1,%2,%3}, {%4,%5,%6,%7}, {%8,%9}, {%0,%1,%2,%3};"
                 : "+f"(d[0]), "+f"(d[1]), "+f"(d[2]), "+f"(d[3])
                 : "r"(a[0]), "r"(a[1]), "r"(a[2]), "r"(a[3]), "r"(b0), "r"(b1));
}

// ---------------- RoPE cos/sin table -------------------------------------------
__global__ void rope_table_kernel() {
    int idx = blockIdx.x * blockDim.x + threadIdx.x;
    if (idx >= TT * (HD/2)) return;
    int t = idx / (HD/2);
    int i = idx % (HD/2);
    float inv = (float)pow(10000.0, -(double)(2*i) / (double)HD);
    float ang = (float)t * inv;
    g_cos[idx] = cosf(ang);
    g_sin[idx] = sinf(ang);
}

// ---------------- fp32 -> (bf16 hi, bf16 lo) split ------------------------------
__global__ void cvt_split_kernel(const float* __restrict__ in,
                                 __nv_bfloat16* __restrict__ hi,
                                 __nv_bfloat16* __restrict__ lo, int n4) {
    int i = blockIdx.x * blockDim.x + threadIdx.x;
    if (i >= n4) return;
    float4 v = ((const float4*)in)[i];
    __nv_bfloat16 h0 = __float2bfloat16(v.x), h1 = __float2bfloat16(v.y);
    __nv_bfloat16 h2 = __float2bfloat16(v.z), h3 = __float2bfloat16(v.w);
    __nv_bfloat16 l0 = __float2bfloat16(v.x - __bfloat162float(h0));
    __nv_bfloat16 l1 = __float2bfloat16(v.y - __bfloat162float(h1));
    __nv_bfloat16 l2 = __float2bfloat16(v.z - __bfloat162float(h2));
    __nv_bfloat16 l3 = __float2bfloat16(v.w - __bfloat162float(h3));
    __nv_bfloat162 hp0(h0, h1), hp1(h2, h3), lp0(l0, l1), lp1(l2, l3);
    ((__nv_bfloat162*)hi)[i*2]   = hp0;
    ((__nv_bfloat162*)hi)[i*2+1] = hp1;
    ((__nv_bfloat162*)lo)[i*2]   = lp0;
    ((__nv_bfloat162*)lo)[i*2+1] = lp1;
}

// ---------------- split-bf16 GEMM via TMA + mma.sync ----------------------------
// CTA 128x256, BK=64, 2-stage TMA pipeline, 8 warps (2m x 4n), warp tile 64x64.
// MODE 0: row-major out; MODE 1: (B,H,T,hd)+RoPE; MODE 2: (B,H,T,hd)
#define BM 128
#define BN 256
#define BK 64
#define NKIT (CC / BK)     // 32
#define AH_OFF 0
#define AL_OFF 16384
#define BH_OFF 32768
#define BL_OFF 65536
#define STG_SZ 98304
#define GEMM_SMEM (2048 + 2*STG_SZ)

// swizzled byte offset within a [rows][128B] k-major tile (== TMA SW128 layout)
__device__ __forceinline__ uint32_t swzoff(int r, int chunk) {
    return (uint32_t)(r * 128 + ((chunk ^ (r & 7)) << 4));
}

template<int MODE>
__global__ __launch_bounds__(256, 1)
void gemm_tma(const __grid_constant__ CUtensorMap tmAh,
              const __grid_constant__ CUtensorMap tmAl,
              const __grid_constant__ CUtensorMap tmBh,
              const __grid_constant__ CUtensorMap tmBl,
              float* __restrict__ out) {
    extern __shared__ char smraw[];
    const uint32_t raw = smem_u32(smraw);
    const uint32_t ab = (raw + 64 + 1023) & ~1023u;
    const uint32_t fullb = raw;         // full[0], full[1] @ raw, raw+8
    const uint32_t emptyb = raw + 16;   // empty[0], empty[1]
    const int tid = threadIdx.x;
    const int wid = tid >> 5, lane = tid & 31;
    const int wm = wid & 1;
    const int wn = wid >> 1;
    const int m0 = blockIdx.y * BM;
    const int n0 = blockIdx.x * BN;

    if (tid == 0) {
        MBAR_INIT(fullb, 1);     MBAR_INIT(fullb + 8, 1);
        MBAR_INIT(emptyb, 256);  MBAR_INIT(emptyb + 8, 256);
        asm volatile("fence.proxy.async.shared::cta;" ::: "memory");
    }
    __syncthreads();

    float acc[4][8][4];
#pragma unroll
    for (int i = 0; i < 4; i++)
#pragma unroll
        for (int j = 0; j < 8; j++)
#pragma unroll
            for (int q = 0; q < 4; q++) acc[i][j][q] = 0.f;

    const int a_row = wm * 64 + (lane & 15);
    const int a_csel = lane >> 4;
    const int b_row = wn * 64 + ((lane >> 4) << 3) + (lane & 7);
    const int b_csel = (lane >> 3) & 1;

    // producer: issue chunk n into stage n&1
    auto issue = [&](int n) {
        int s = n & 1;
        uint32_t sb = ab + s * STG_SZ;
        uint32_t mb = fullb + s * 8;
        MBAR_EXPECT(mb, (uint32_t)STG_SZ);
        int cx = n * BK;
        TMA2D(sb + AH_OFF, &tmAh, cx, m0, mb);
        TMA2D(sb + AL_OFF, &tmAl, cx, m0, mb);
        TMA2D(sb + BH_OFF, &tmBh, cx, n0, mb);
        TMA2D(sb + BL_OFF, &tmBl, cx, n0, mb);
    };

    if (tid == 0) issue(0);

    for (int c = 0; c < NKIT; ++c) {
        int s = c & 1;
        if (tid == 0 && c + 1 < NKIT) {
            int n = c + 1;
            if (n >= 2) MBAR_WAIT(emptyb + (n & 1) * 8, ((n >> 1) - 1) & 1);
            issue(n);
        }
        MBAR_WAIT(fullb + s * 8, (c >> 1) & 1);

        uint32_t sb = ab + s * STG_SZ;
#pragma unroll
        for (int ks = 0; ks < 4; ks++) {
            uint32_t ah[4][4], al[4][4], bh[4][4], bl[4][4];
#pragma unroll
            for (int f = 0; f < 4; f++) {
                int r = a_row + f * 16;
                uint32_t off = swzoff(r, 2 * ks + a_csel);
                ldmx4(ah[f], sb + AH_OFF + off);
                ldmx4(al[f], sb + AL_OFF + off);
            }
#pragma unroll
            for (int p = 0; p < 4; p++) {
                int r = b_row + p * 16;
                uint32_t off = swzoff(r, 2 * ks + b_csel);
                ldmx4(bh[p], sb + BH_OFF + off);
                ldmx4(bl[p], sb + BL_OFF + off);
            }
#pragma unroll
            for (int mf = 0; mf < 4; mf++)
#pragma unroll
                for (int nf = 0; nf < 8; nf++) {
                    int p = nf >> 1;
                    int e = (nf & 1) << 1;
                    mma16816(acc[mf][nf], ah[mf], bh[p][e], bh[p][e + 1]);
                    mma16816(acc[mf][nf], ah[mf], bl[p][e], bl[p][e + 1]);
                    mma16816(acc[mf][nf], al[mf], bh[p][e], bh[p][e + 1]);
                }
        }
        MBAR_ARRIVE(emptyb + s * 8);
    }

    // ---- epilogue: direct stores (d0,d1 is an even/odd RoPE pair) ----
    const int tr = lane >> 2;
    const int tc = (lane & 3) << 1;
#pragma unroll
    for (int mf = 0; mf < 4; mf++) {
#pragma unroll
        for (int nf = 0; nf < 8; nf++) {
            int mA = m0 + wm * 64 + mf * 16 + tr;
            int n  = n0 + wn * 64 + nf * 8 + tc;
            float* d = acc[mf][nf];
#pragma unroll
            for (int half = 0; half < 2; half++) {
                int m = mA + half * 8;
                float e = d[half * 2], o = d[half * 2 + 1];
                if (MODE == 0) {
                    float2 v2 = {e, o};
                    *(float2*)(out + (size_t)m * CC + n) = v2;
                } else {
                    int b = m >> 11;
                    int t = m & (TT - 1);
                    int h = n >> 7;
                    int dd = n & (HD - 1);
                    size_t dst = ((size_t)(b * NH + h) * TT + t) * HD + dd;
                    if (MODE == 1) {
                        float cv = g_cos[t * (HD/2) + (dd >> 1)];
                        float sv = g_sin[t * (HD/2) + (dd >> 1)];
                        float2 v2 = {e * cv - o * sv, o * cv + e * sv};
                        *(float2*)(out + dst) = v2;
                    } else {
                        float2 v2 = {e, o};
                        *(float2*)(out + dst) = v2;
                    }
                }
            }
        }
    }
}

// ---------------- Flash attention (fp32, causal) -------------------------------
#define ABM 64
#define QLD 132
#define PLD 68
#define SMEM_ATTN ((ABM*QLD*2 + ABM*PLD) * 4)

__global__ __launch_bounds__(256, 2)
void attn_kernel() {
    extern __shared__ float smf[];
    float* Qs = smf;
    float* Ts = smf + ABM * QLD;
    float* Ps = smf + 2 * ABM * QLD;

    int qtile = blockIdx.x;
    int bh    = blockIdx.y;
    int tid = threadIdx.x;
    int ty = tid >> 4, tx = tid & 15;
    const float scale = 0.08838834764831843f;

    const float* Qb = g_q + (size_t)bh * TT * HD + (size_t)qtile * ABM * HD;
    const float* Kb = g_k + (size_t)bh * TT * HD;
    const float* Vb = g_v + (size_t)bh * TT * HD;

    for (int i = tid; i < ABM * 32; i += 256) {
        int row = i >> 5, c4 = (i & 31) << 2;
        float4 v = *(const float4*)(Qb + row * HD + c4);
        float* d = &Qs[row * QLD + c4];
        d[0] = v.x * scale; d[1] = v.y * scale;
        d[2] = v.z * scale; d[3] = v.w * scale;
    }

    float o[4][8];
    float m_i[4], l_i[4];
#pragma unroll
    for (int r = 0; r < 4; r++) {
        m_i[r] = -1e30f; l_i[r] = 0.f;
#pragma unroll
        for (int c = 0; c < 8; c++) o[r][c] = 0.f;
    }

    int ntiles = qtile + 1;
    for (int j = 0; j < ntiles; j++) {
        __syncthreads();
        const float* Kt = Kb + (size_t)j * ABM * HD;
        for (int i = tid; i < ABM * 32; i += 256) {
            int row = i >> 5, c4 = (i & 31) << 2;
            *(float4*)&Ts[row * QLD + c4] = *(const float4*)(Kt + row * HD + c4);
        }
        __syncthreads();

        float s[4][4];
#pragma unroll
        for (int r = 0; r < 4; r++)
#pragma unroll
            for (int c = 0; c < 4; c++) s[r][c] = 0.f;

#pragma unroll 2
        for (int kk = 0; kk < HD; kk += 4) {
            float4 qv[4], kv[4];
#pragma unroll
            for (int r = 0; r < 4; r++)
                qv[r] = *(const float4*)&Qs[((ty << 2) + r) * QLD + kk];
#pragma unroll
            for (int c = 0; c < 4; c++)
                kv[c] = *(const float4*)&Ts[(tx + (c << 4)) * QLD + kk];
#pragma unroll
            for (int r = 0; r < 4; r++)
#pragma unroll
                for (int c = 0; c < 4; c++) {
                    s[r][c] = fmaf(qv[r].x, kv[c].x, s[r][c]);
                    s[r][c] = fmaf(qv[r].y, kv[c].y, s[r][c]);
                    s[r][c] = fmaf(qv[r].z, kv[c].z, s[r][c]);
                    s[r][c] = fmaf(qv[r].w, kv[c].w, s[r][c]);
                }
        }

        if (j == qtile) {
#pragma unroll
            for (int r = 0; r < 4; r++)
#pragma unroll
                for (int c = 0; c < 4; c++)
                    if (tx + (c << 4) > (ty << 2) + r) s[r][c] = -1e30f;
        }

#pragma unroll
        for (int r = 0; r < 4; r++) {
            float rm = fmaxf(fmaxf(s[r][0], s[r][1]), fmaxf(s[r][2], s[r][3]));
#pragma unroll
            for (int off = 1; off < 16; off <<= 1)
                rm = fmaxf(rm, __shfl_xor_sync(0xffffffffu, rm, off));
            float mn = fmaxf(m_i[r], rm);
            float alpha = __expf(m_i[r] - mn);
            float p[4], rs = 0.f;
#pragma unroll
            for (int c = 0; c < 4; c++) { p[c] = __expf(s[r][c] - mn); rs += p[c]; }
#pragma unroll
            for (int off = 1; off < 16; off <<= 1)
                rs += __shfl_xor_sync(0xffffffffu, rs, off);
            l_i[r] = l_i[r] * alpha + rs;
            m_i[r] = mn;
#pragma unroll
            for (int c = 0; c < 8; c++) o[r][c] *= alpha;
#pragma unroll
            for (int c = 0; c < 4; c++)
                Ps[((ty << 2) + r) * PLD + tx + (c << 4)] = p[c];
        }
        __syncthreads();

        const float* Vt = Vb + (size_t)j * ABM * HD;
        for (int i = tid; i < ABM * 32; i += 256) {
            int row = i >> 5, c4 = (i & 31) << 2;
            *(float4*)&Ts[row * QLD + c4] = *(const float4*)(Vt + row * HD + c4);
        }
        __syncthreads();

#pragma unroll 2
        for (int kk = 0; kk < ABM; kk += 4) {
            float pvals[4][4];
#pragma unroll
            for (int r = 0; r < 4; r++) {
                float4 t4 = *(const float4*)&Ps[((ty << 2) + r) * PLD + kk];
                pvals[r][0] = t4.x; pvals[r][1] = t4.y;
                pvals[r][2] = t4.z; pvals[r][3] = t4.w;
            }
#pragma unroll
            for (int q = 0; q < 4; q++) {
                float vr[8];
#pragma unroll
                for (int c = 0; c < 8; c++)
                    vr[c] = Ts[(kk + q) * QLD + tx + (c << 4)];
#pragma unroll
                for (int r = 0; r < 4; r++)
#pragma unroll
                    for (int c = 0; c < 8; c++)
                        o[r][c] = fmaf(pvals[r][q], vr[c], o[r][c]);
            }
        }
    }

    int b = bh >> 4, h = bh & 15;
#pragma unroll
    for (int r = 0; r < 4; r++) {
        int tq = qtile * ABM + (ty << 2) + r;
        float inv = 1.0f / l_i[r];
#pragma unroll
        for (int c = 0; c < 8; c++) {
            int d = tx + (c << 4);
            g_y[(size_t)(b * TT + tq) * CC + h * HD + d] = o[r][c] * inv;
        }
    }
}

// ---------------- host: tensormap encode via driver entry point ------------------
typedef CUresult (*EncodeFn)(CUtensorMap*, CUtensorMapDataType, cuuint32_t, void*,
                             const cuuint64_t*, const cuuint64_t*, const cuuint32_t*,
                             const cuuint32_t*, CUtensorMapInterleave, CUtensorMapSwizzle,
                             CUtensorMapL2promotion, CUtensorMapFloatOOBfill);

static void mk_map(EncodeFn enc, CUtensorMap* m, void* base, uint64_t rows, uint32_t boxRows) {
    cuuint64_t dims[2] = {(cuuint64_t)CC, (cuuint64_t)rows};
    cuuint64_t strides[1] = {(cuuint64_t)CC * 2};
    cuuint32_t box[2] = {64u, boxRows};
    cuuint32_t es[2] = {1u, 1u};
    enc(m, CU_TENSOR_MAP_DATA_TYPE_BFLOAT16, 2, base, dims, strides, box, es,
        CU_TENSOR_MAP_INTERLEAVE_NONE, CU_TENSOR_MAP_SWIZZLE_128B,
        CU_TENSOR_MAP_L2_PROMOTION_L2_128B, CU_TENSOR_MAP_FLOAT_OOB_FILL_NONE);
}

// ---------------- launch --------------------------------------------------------
extern "C" void kernel_launch(void* const* d_in, const int* in_sizes, int n_in,
                              void* d_out, int out_size) {
    const float* x  = (const float*)d_in[0];
    const float* Wq = (const float*)d_in[1];
    const float* Wk = (const float*)d_in[2];
    const float* Wv = (const float*)d_in[3];
    const float* Wp = (const float*)d_in[4];
    float* out = (float*)d_out;

    float *qp, *kp, *vp, *yp;
    cudaGetSymbolAddress((void**)&qp, g_q);
    cudaGetSymbolAddress((void**)&kp, g_k);
    cudaGetSymbolAddress((void**)&vp, g_v);
    cudaGetSymbolAddress((void**)&yp, g_y);
    __nv_bfloat16 *xh, *xl, *yh, *yl, *wh, *wl;
    cudaGetSymbolAddress((void**)&xh, g_xh);
    cudaGetSymbolAddress((void**)&xl, g_xl);
    cudaGetSymbolAddress((void**)&yh, g_yh);
    cudaGetSymbolAddress((void**)&yl, g_yl);
    cudaGetSymbolAddress((void**)&wh, g_wh);
    cudaGetSymbolAddress((void**)&wl, g_wl);

    // tensormaps (host-side, by value -> __grid_constant__)
    void* fn = nullptr;
    cudaDriverEntryPointQueryResult st;
    cudaGetDriverEntryPoint("cuTensorMapEncodeTiled", &fn, cudaEnableDefault, &st);
    EncodeFn enc = (EncodeFn)fn;
    CUtensorMap mXh, mXl, mYh, mYl, mWh[4], mWl[4];
    mk_map(enc, &mXh, xh, MM, BM);
    mk_map(enc, &mXl, xl, MM, BM);
    mk_map(enc, &mYh, yh, MM, BM);
    mk_map(enc, &mYl, yl, MM, BM);
    for (int i = 0; i < 4; i++) {
        mk_map(enc, &mWh[i], wh + (size_t)i * CC * CC, CC, BN);
        mk_map(enc, &mWl[i], wl + (size_t)i * CC * CC, CC, BN);
    }

    rope_table_kernel<<<(TT * (HD/2) + 255) / 256, 256>>>();

    const int NX4 = MM * CC / 4;
    const int NW4 = CC * CC / 4;
    cvt_split_kernel<<<(NX4 + 255) / 256, 256>>>(x, xh, xl, NX4);
    const float* Ws[4] = {Wq, Wk, Wv, Wp};
    for (int i = 0; i < 4; i++)
        cvt_split_kernel<<<(NW4 + 255) / 256, 256>>>(Ws[i], wh + (size_t)i * CC * CC,
                                                     wl + (size_t)i * CC * CC, NW4);

    cudaFuncSetAttribute(gemm_tma<0>, cudaFuncAttributeMaxDynamicSharedMemorySize, GEMM_SMEM);
    cudaFuncSetAttribute(gemm_tma<1>, cudaFuncAttributeMaxDynamicSharedMemorySize, GEMM_SMEM);
    cudaFuncSetAttribute(gemm_tma<2>, cudaFuncAttributeMaxDynamicSharedMemorySize, GEMM_SMEM);

    dim3 gg(CC / BN, MM / BM);     // (8, 64)
    gemm_tma<1><<<gg, 256, GEMM_SMEM>>>(mXh, mXl, mWh[0], mWl[0], qp);
    gemm_tma<1><<<gg, 256, GEMM_SMEM>>>(mXh, mXl, mWh[1], mWl[1], kp);
    gemm_tma<2><<<gg, 256, GEMM_SMEM>>>(mXh, mXl, mWh[2], mWl[2], vp);

    cudaFuncSetAttribute(attn_kernel, cudaFuncAttributeMaxDynamicSharedMemorySize, SMEM_ATTN);
    attn_kernel<<<dim3(TT / ABM, BSZ * NH), 256, SMEM_ATTN>>>();

    cvt_split_kernel<<<(NX4 + 255) / 256, 256>>>(yp, yh, yl, NX4);
    gemm_tma<0><<<gg, 256, GEMM_SMEM>>>(mYh, mYl, mWh[3], mWl[3], out);
}

// round 5
// speedup vs baseline: 3.3018x; 1.6279x over previous
#include <cuda_runtime.h>
#include <cuda.h>
#include <cuda_bf16.h>
#include <math.h>
#include <cstdint>

#define BSZ 4
#define TT 2048
#define CC 2048
#define NH 16
#define HD 128
#define MM (BSZ*TT)   // 8192

// ---------------- scratch (device globals: no allocation allowed) -------------
__device__ float g_cos[TT*(HD/2)];
__device__ float g_sin[TT*(HD/2)];
// split-bf16 operand buffers (1KB aligned for TMA)
__device__ __align__(1024) __nv_bfloat16 g_xh[(size_t)MM*CC];
__device__ __align__(1024) __nv_bfloat16 g_xl[(size_t)MM*CC];
__device__ __align__(1024) __nv_bfloat16 g_yh[(size_t)MM*CC];
__device__ __align__(1024) __nv_bfloat16 g_yl[(size_t)MM*CC];
__device__ __align__(1024) __nv_bfloat16 g_wh[4][(size_t)CC*CC];
__device__ __align__(1024) __nv_bfloat16 g_wl[4][(size_t)CC*CC];
// q/k/v in (B,H,T,hd) split bf16
__device__ __align__(1024) __nv_bfloat16 g_qh[(size_t)BSZ*NH*TT*HD];
__device__ __align__(1024) __nv_bfloat16 g_ql[(size_t)BSZ*NH*TT*HD];
__device__ __align__(1024) __nv_bfloat16 g_kh[(size_t)BSZ*NH*TT*HD];
__device__ __align__(1024) __nv_bfloat16 g_kl[(size_t)BSZ*NH*TT*HD];
__device__ __align__(1024) __nv_bfloat16 g_vh[(size_t)BSZ*NH*TT*HD];
__device__ __align__(1024) __nv_bfloat16 g_vl[(size_t)BSZ*NH*TT*HD];

// ---------------- PTX helpers --------------------------------------------------
__device__ __forceinline__ uint32_t smem_u32(const void* p) {
    uint32_t a;
    asm("{ .reg .u64 t; cvta.to.shared.u64 t, %1; cvt.u32.u64 %0, t; }" : "=r"(a) : "l"(p));
    return a;
}
#define MBAR_INIT(a, n) asm volatile("mbarrier.init.shared.b64 [%0], %1;" :: "r"(a), "r"(n) : "memory")
#define MBAR_ARRIVE(a)  asm volatile("mbarrier.arrive.shared.b64 _, [%0];" :: "r"(a) : "memory")
#define MBAR_EXPECT(a, tx) asm volatile("mbarrier.arrive.expect_tx.shared.b64 _, [%0], %1;" :: "r"(a), "r"(tx) : "memory")
#define MBAR_WAIT(a, ph) do {                                                      \
    uint32_t _m = (a), _p = (ph), _d;                                              \
    asm volatile("{\n\t.reg .pred p;\n\t"                                          \
        "mbarrier.try_wait.parity.acquire.cta.shared::cta.b64 p, [%1], %2;\n\t"    \
        "selp.b32 %0, 1, 0, p;\n\t}" : "=r"(_d) : "r"(_m), "r"(_p) : "memory");    \
    if (!_d) {                                                                     \
        asm volatile("{\n\t.reg .pred P1;\n\t"                                     \
            "WL_%=:\n\t"                                                           \
            "mbarrier.try_wait.parity.acquire.cta.shared::cta.b64 P1, [%0], %1, 0x989680;\n\t" \
            "@P1 bra.uni WD_%=;\n\tbra.uni WL_%=;\n\tWD_%=:\n\t}"                  \
            :: "r"(_m), "r"(_p) : "memory");                                       \
    }                                                                              \
} while (0)
#define TMA2D(dst, map, cx, cy, mb) \
    asm volatile("cp.async.bulk.tensor.2d.shared::cta.global.tile.mbarrier::complete_tx::bytes " \
        "[%0], [%1, {%2, %3}], [%4];" \
        :: "r"(dst), "l"(map), "r"(cx), "r"(cy), "r"(mb) : "memory")

__device__ __forceinline__ void ldmx4(uint32_t* r, uint32_t addr) {
    asm volatile("ldmatrix.sync.aligned.m8n8.x4.shared.b16 {%0,%1,%2,%3}, [%4];"
                 : "=r"(r[0]), "=r"(r[1]), "=r"(r[2]), "=r"(r[3]) : "r"(addr));
}
__device__ __forceinline__ void ldmx4t(uint32_t* r, uint32_t addr) {
    asm volatile("ldmatrix.sync.aligned.m8n8.x4.trans.shared.b16 {%0,%1,%2,%3}, [%4];"
                 : "=r"(r[0]), "=r"(r[1]), "=r"(r[2]), "=r"(r[3]) : "r"(addr));
}
__device__ __forceinline__ void mma16816(float* d, const uint32_t* a,
                                         uint32_t b0, uint32_t b1) {
    asm volatile("mma.sync.aligned.m16n8k16.row.col.f32.bf16.bf16.f32 "
                 "{%0,%1,%2,%3}, {%4,%5,%6,%7}, {%8,%9}, {%0,%1,%2,%3};"
                 : "+f"(d[0]), "+f"(d[1]), "+f"(d[2]), "+f"(d[3])
                 : "r"(a[0]), "r"(a[1]), "r"(a[2]), "r"(a[3]), "r"(b0), "r"(b1));
}
// pack two floats -> bf16x2 {lo, hi}
__device__ __forceinline__ uint32_t packbf(float lo, float hi) {
    uint32_t r;
    asm("cvt.rn.bf16x2.f32 %0, %1, %2;" : "=r"(r) : "f"(hi), "f"(lo));
    return r;
}
__device__ __forceinline__ float bfval(float x) {
    return __bfloat162float(__float2bfloat16(x));
}
// swizzled byte offset within a [rows][128B] k-major tile (== TMA SW128 layout)
__device__ __forceinline__ uint32_t swzoff(int r, int chunk) {
    return (uint32_t)(r * 128 + ((chunk ^ (r & 7)) << 4));
}

// ---------------- RoPE cos/sin table -------------------------------------------
__global__ void rope_table_kernel() {
    int idx = blockIdx.x * blockDim.x + threadIdx.x;
    if (idx >= TT * (HD/2)) return;
    int t = idx / (HD/2);
    int i = idx % (HD/2);
    float inv = (float)pow(10000.0, -(double)(2*i) / (double)HD);
    float ang = (float)t * inv;
    g_cos[idx] = cosf(ang);
    g_sin[idx] = sinf(ang);
}

// ---------------- fp32 -> (bf16 hi, bf16 lo) split ------------------------------
__global__ void cvt_split_kernel(const float* __restrict__ in,
                                 __nv_bfloat16* __restrict__ hi,
                                 __nv_bfloat16* __restrict__ lo, int n4) {
    int i = blockIdx.x * blockDim.x + threadIdx.x;
    if (i >= n4) return;
    float4 v = ((const float4*)in)[i];
    uint32_t h0 = packbf(v.x, v.y), h1 = packbf(v.z, v.w);
    uint32_t l0 = packbf(v.x - bfval(v.x), v.y - bfval(v.y));
    uint32_t l1 = packbf(v.z - bfval(v.z), v.w - bfval(v.w));
    ((uint32_t*)hi)[i*2]   = h0;
    ((uint32_t*)hi)[i*2+1] = h1;
    ((uint32_t*)lo)[i*2]   = l0;
    ((uint32_t*)lo)[i*2+1] = l1;
}

// ---------------- split-bf16 GEMM via TMA + mma.sync ----------------------------
// CTA 128x256, BK=64, 2-stage TMA pipeline, 8 warps (2m x 4n), warp tile 64x64.
// MODE 0: fp32 row-major out; MODE 1: (B,H,T,hd)+RoPE split bf16; MODE 2: split bf16
#define BM 128
#define BN 256
#define BK 64
#define NKIT (CC / BK)     // 32
#define AH_OFF 0
#define AL_OFF 16384
#define BH_OFF 32768
#define BL_OFF 65536
#define STG_SZ 98304
#define GEMM_SMEM (2048 + 2*STG_SZ)

template<int MODE>
__global__ __launch_bounds__(256, 1)
void gemm_tma(const __grid_constant__ CUtensorMap tmAh,
              const __grid_constant__ CUtensorMap tmAl,
              const __grid_constant__ CUtensorMap tmBh,
              const __grid_constant__ CUtensorMap tmBl,
              float* __restrict__ out,
              __nv_bfloat16* __restrict__ outH,
              __nv_bfloat16* __restrict__ outL) {
    extern __shared__ char smraw[];
    const uint32_t raw = smem_u32(smraw);
    const uint32_t ab = (raw + 64 + 1023) & ~1023u;
    const uint32_t fullb = raw;
    const uint32_t emptyb = raw + 16;
    const int tid = threadIdx.x;
    const int wid = tid >> 5, lane = tid & 31;
    const int wm = wid & 1;
    const int wn = wid >> 1;
    const int m0 = blockIdx.y * BM;
    const int n0 = blockIdx.x * BN;

    if (tid == 0) {
        MBAR_INIT(fullb, 1);     MBAR_INIT(fullb + 8, 1);
        MBAR_INIT(emptyb, 256);  MBAR_INIT(emptyb + 8, 256);
        asm volatile("fence.proxy.async.shared::cta;" ::: "memory");
    }
    __syncthreads();

    float acc[4][8][4];
#pragma unroll
    for (int i = 0; i < 4; i++)
#pragma unroll
        for (int j = 0; j < 8; j++)
#pragma unroll
            for (int q = 0; q < 4; q++) acc[i][j][q] = 0.f;

    const int a_row = wm * 64 + (lane & 15);
    const int a_csel = lane >> 4;
    const int b_row = wn * 64 + ((lane >> 4) << 3) + (lane & 7);
    const int b_csel = (lane >> 3) & 1;

    auto issue = [&](int n) {
        int s = n & 1;
        uint32_t sb = ab + s * STG_SZ;
        uint32_t mb = fullb + s * 8;
        MBAR_EXPECT(mb, (uint32_t)STG_SZ);
        int cx = n * BK;
        TMA2D(sb + AH_OFF, &tmAh, cx, m0, mb);
        TMA2D(sb + AL_OFF, &tmAl, cx, m0, mb);
        TMA2D(sb + BH_OFF, &tmBh, cx, n0, mb);
        TMA2D(sb + BL_OFF, &tmBl, cx, n0, mb);
    };

    if (tid == 0) issue(0);

    for (int c = 0; c < NKIT; ++c) {
        int s = c & 1;
        if (tid == 0 && c + 1 < NKIT) {
            int n = c + 1;
            if (n >= 2) MBAR_WAIT(emptyb + (n & 1) * 8, ((n >> 1) - 1) & 1);
            issue(n);
        }
        MBAR_WAIT(fullb + s * 8, (c >> 1) & 1);

        uint32_t sb = ab + s * STG_SZ;
#pragma unroll
        for (int ks = 0; ks < 4; ks++) {
            uint32_t ah[4][4], al[4][4], bh[4][4], bl[4][4];
#pragma unroll
            for (int f = 0; f < 4; f++) {
                int r = a_row + f * 16;
                uint32_t off = swzoff(r, 2 * ks + a_csel);
                ldmx4(ah[f], sb + AH_OFF + off);
                ldmx4(al[f], sb + AL_OFF + off);
            }
#pragma unroll
            for (int p = 0; p < 4; p++) {
                int r = b_row + p * 16;
                uint32_t off = swzoff(r, 2 * ks + b_csel);
                ldmx4(bh[p], sb + BH_OFF + off);
                ldmx4(bl[p], sb + BL_OFF + off);
            }
#pragma unroll
            for (int mf = 0; mf < 4; mf++)
#pragma unroll
                for (int nf = 0; nf < 8; nf++) {
                    int p = nf >> 1;
                    int e = (nf & 1) << 1;
                    mma16816(acc[mf][nf], ah[mf], bh[p][e], bh[p][e + 1]);
                    mma16816(acc[mf][nf], ah[mf], bl[p][e], bl[p][e + 1]);
                    mma16816(acc[mf][nf], al[mf], bh[p][e], bh[p][e + 1]);
                }
        }
        MBAR_ARRIVE(emptyb + s * 8);
    }

    // ---- epilogue ----
    const int tr = lane >> 2;
    const int tc = (lane & 3) << 1;
#pragma unroll
    for (int mf = 0; mf < 4; mf++) {
#pragma unroll
        for (int nf = 0; nf < 8; nf++) {
            int mA = m0 + wm * 64 + mf * 16 + tr;
            int n  = n0 + wn * 64 + nf * 8 + tc;
            float* d = acc[mf][nf];
#pragma unroll
            for (int half = 0; half < 2; half++) {
                int m = mA + half * 8;
                float e = d[half * 2], o = d[half * 2 + 1];
                if (MODE == 0) {
                    float2 v2 = {e, o};
                    *(float2*)(out + (size_t)m * CC + n) = v2;
                } else {
                    int b = m >> 11;
                    int t = m & (TT - 1);
                    int h = n >> 7;
                    int dd = n & (HD - 1);
                    size_t dst = ((size_t)(b * NH + h) * TT + t) * HD + dd;
                    float e2 = e, o2 = o;
                    if (MODE == 1) {
                        float cv = g_cos[t * (HD/2) + (dd >> 1)];
                        float sv = g_sin[t * (HD/2) + (dd >> 1)];
                        e2 = e * cv - o * sv;
                        o2 = o * cv + e * sv;
                    }
                    *(uint32_t*)((char*)outH + dst * 2) = packbf(e2, o2);
                    *(uint32_t*)((char*)outL + dst * 2) =
                        packbf(e2 - bfval(e2), o2 - bfval(o2));
                }
            }
        }
    }
}

// ---------------- tensor-core flash attention (split bf16, causal) --------------
// CTA: 64 q rows, 64-key tiles, 4 warps (16 q rows each), 128 threads, 2 CTAs/SM.
#define SQH 0
#define SQL 16384
#define SKH 32768
#define SKL 49152
#define SVH 65536
#define SVL 81920
#define ATTN_SMEM (1024 + 98304)

__global__ __launch_bounds__(128, 2)
void attn_tc(const __grid_constant__ CUtensorMap mQh,
             const __grid_constant__ CUtensorMap mQl,
             const __grid_constant__ CUtensorMap mKh,
             const __grid_constant__ CUtensorMap mKl,
             const __grid_constant__ CUtensorMap mVh,
             const __grid_constant__ CUtensorMap mVl,
             __nv_bfloat16* __restrict__ yh,
             __nv_bfloat16* __restrict__ yl) {
    extern __shared__ char smraw[];
    const uint32_t raw = smem_u32(smraw);
    const uint32_t ab = (raw + 64 + 1023) & ~1023u;
    const uint32_t qfull = raw, kfull = raw + 8, vfull = raw + 16;
    const uint32_t kempty = raw + 24, vempty = raw + 32;
    const int tid = threadIdx.x, wid = tid >> 5, lane = tid & 31;
    const int qtile = blockIdx.x, bh = blockIdx.y;
    const int nt = qtile + 1;
    const int grow_q = bh * TT + qtile * 64;
    const int grow_k = bh * TT;

    if (tid == 0) {
        MBAR_INIT(qfull, 1); MBAR_INIT(kfull, 1); MBAR_INIT(vfull, 1);
        MBAR_INIT(kempty, 128); MBAR_INIT(vempty, 128);
        asm volatile("fence.proxy.async.shared::cta;" ::: "memory");
    }
    __syncthreads();
    if (tid == 0) {
        MBAR_EXPECT(qfull, 32768u);
        TMA2D(ab + SQH,        &mQh, 0,  grow_q, qfull);
        TMA2D(ab + SQH + 8192, &mQh, 64, grow_q, qfull);
        TMA2D(ab + SQL,        &mQl, 0,  grow_q, qfull);
        TMA2D(ab + SQL + 8192, &mQl, 64, grow_q, qfull);
        MBAR_EXPECT(kfull, 32768u);
        TMA2D(ab + SKH,        &mKh, 0,  grow_k, kfull);
        TMA2D(ab + SKH + 8192, &mKh, 64, grow_k, kfull);
        TMA2D(ab + SKL,        &mKl, 0,  grow_k, kfull);
        TMA2D(ab + SKL + 8192, &mKl, 64, grow_k, kfull);
        MBAR_EXPECT(vfull, 32768u);
        TMA2D(ab + SVH,        &mVh, 0,  grow_k, vfull);
        TMA2D(ab + SVH + 8192, &mVh, 64, grow_k, vfull);
        TMA2D(ab + SVL,        &mVl, 0,  grow_k, vfull);
        TMA2D(ab + SVL + 8192, &mVl, 64, grow_k, vfull);
    }

    float o[16][4];
#pragma unroll
    for (int i = 0; i < 16; i++)
#pragma unroll
        for (int q = 0; q < 4; q++) o[i][q] = 0.f;
    float m0r = -1e30f, m1r = -1e30f, l0r = 0.f, l1r = 0.f;

    const int q_row = wid * 16 + (lane & 15);
    const int q_csel = lane >> 4;
    const int k_rowbase = ((lane >> 4) << 3) + (lane & 7);
    const int k_csel = (lane >> 3) & 1;
    const int v_rowin = (lane & 7) + (((lane >> 3) & 1) << 3);
    const int v_csel = lane >> 4;
    const float scale = 0.08838834764831843f;

    MBAR_WAIT(qfull, 0);

    for (int j = 0; j < nt; j++) {
        MBAR_WAIT(kfull, j & 1);

        float s[8][4];
#pragma unroll
        for (int nf = 0; nf < 8; nf++)
#pragma unroll
            for (int q = 0; q < 4; q++) s[nf][q] = 0.f;

#pragma unroll
        for (int ks = 0; ks < 8; ks++) {
            int half = ks >> 2;
            int lc = (ks & 3) << 1;
            uint32_t qh4[4], ql4[4];
            uint32_t qoff = half * 8192 + swzoff(q_row, lc + q_csel);
            ldmx4(qh4, ab + SQH + qoff);
            ldmx4(ql4, ab + SQL + qoff);
#pragma unroll
            for (int p = 0; p < 4; p++) {
                uint32_t kh4[4], kl4[4];
                uint32_t koff = half * 8192 + swzoff(p * 16 + k_rowbase, lc + k_csel);
                ldmx4(kh4, ab + SKH + koff);
                ldmx4(kl4, ab + SKL + koff);
#pragma unroll
                for (int e2 = 0; e2 < 2; e2++) {
                    int nf = p * 2 + e2;
                    int e = e2 << 1;
                    mma16816(s[nf], qh4, kh4[e], kh4[e + 1]);
                    mma16816(s[nf], qh4, kl4[e], kl4[e + 1]);
                    mma16816(s[nf], ql4, kh4[e], kh4[e + 1]);
                }
            }
        }
        MBAR_ARRIVE(kempty);
        if (tid == 0 && j + 1 < nt) {
            MBAR_WAIT(kempty, j & 1);
            MBAR_EXPECT(kfull, 32768u);
            int cy = grow_k + (j + 1) * 64;
            TMA2D(ab + SKH,        &mKh, 0,  cy, kfull);
            TMA2D(ab + SKH + 8192, &mKh, 64, cy, kfull);
            TMA2D(ab + SKL,        &mKl, 0,  cy, kfull);
            TMA2D(ab + SKL + 8192, &mKl, 64, cy, kfull);
        }

        // scale + mask
#pragma unroll
        for (int nf = 0; nf < 8; nf++)
#pragma unroll
            for (int q = 0; q < 4; q++) s[nf][q] *= scale;
        if (j == qtile) {
            int r0 = wid * 16 + (lane >> 2);
#pragma unroll
            for (int nf = 0; nf < 8; nf++) {
                int c0 = nf * 8 + ((lane & 3) << 1);
                if (c0     > r0)     s[nf][0] = -1e30f;
                if (c0 + 1 > r0)     s[nf][1] = -1e30f;
                if (c0     > r0 + 8) s[nf][2] = -1e30f;
                if (c0 + 1 > r0 + 8) s[nf][3] = -1e30f;
            }
        }

        // online softmax
        float rm0 = -1e30f, rm1 = -1e30f;
#pragma unroll
        for (int nf = 0; nf < 8; nf++) {
            rm0 = fmaxf(rm0, fmaxf(s[nf][0], s[nf][1]));
            rm1 = fmaxf(rm1, fmaxf(s[nf][2], s[nf][3]));
        }
        rm0 = fmaxf(rm0, __shfl_xor_sync(0xffffffffu, rm0, 1));
        rm0 = fmaxf(rm0, __shfl_xor_sync(0xffffffffu, rm0, 2));
        rm1 = fmaxf(rm1, __shfl_xor_sync(0xffffffffu, rm1, 1));
        rm1 = fmaxf(rm1, __shfl_xor_sync(0xffffffffu, rm1, 2));
        float mn0 = fmaxf(m0r, rm0), mn1 = fmaxf(m1r, rm1);
        float al0 = __expf(m0r - mn0), al1 = __expf(m1r - mn1);
        m0r = mn0; m1r = mn1;

        float rs0 = 0.f, rs1 = 0.f;
        uint32_t aph[4][4], apl[4][4];
#pragma unroll
        for (int ks2 = 0; ks2 < 4; ks2++) {
#pragma unroll
            for (int hn = 0; hn < 2; hn++) {
                int nf = 2 * ks2 + hn;
                float p0 = __expf(s[nf][0] - mn0);
                float p1 = __expf(s[nf][1] - mn0);
                float p2 = __expf(s[nf][2] - mn1);
                float p3 = __expf(s[nf][3] - mn1);
                rs0 += p0 + p1; rs1 += p2 + p3;
                aph[ks2][hn * 2]     = packbf(p0, p1);
                aph[ks2][hn * 2 + 1] = packbf(p2, p3);
                apl[ks2][hn * 2]     = packbf(p0 - bfval(p0), p1 - bfval(p1));
                apl[ks2][hn * 2 + 1] = packbf(p2 - bfval(p2), p3 - bfval(p3));
            }
        }
        rs0 += __shfl_xor_sync(0xffffffffu, rs0, 1);
        rs0 += __shfl_xor_sync(0xffffffffu, rs0, 2);
        rs1 += __shfl_xor_sync(0xffffffffu, rs1, 1);
        rs1 += __shfl_xor_sync(0xffffffffu, rs1, 2);
        l0r = l0r * al0 + rs0;
        l1r = l1r * al1 + rs1;

#pragma unroll
        for (int ng = 0; ng < 16; ng++) {
            o[ng][0] *= al0; o[ng][1] *= al0;
            o[ng][2] *= al1; o[ng][3] *= al1;
        }

        MBAR_WAIT(vfull, j & 1);
#pragma unroll
        for (int ks2 = 0; ks2 < 4; ks2++) {
#pragma unroll
            for (int g = 0; g < 8; g++) {
                uint32_t vh4[4], vl4[4];
                int half = g >> 2;
                uint32_t voff = half * 8192 +
                                swzoff(ks2 * 16 + v_rowin, ((g & 3) << 1) + v_csel);
                ldmx4t(vh4, ab + SVH + voff);
                ldmx4t(vl4, ab + SVL + voff);
#pragma unroll
                for (int e2 = 0; e2 < 2; e2++) {
                    int ng = g * 2 + e2;
                    int e = e2 << 1;
                    mma16816(o[ng], aph[ks2], vh4[e], vh4[e + 1]);
                    mma16816(o[ng], aph[ks2], vl4[e], vl4[e + 1]);
                    mma16816(o[ng], apl[ks2], vh4[e], vh4[e + 1]);
                }
            }
        }
        MBAR_ARRIVE(vempty);
        if (tid == 0 && j + 1 < nt) {
            MBAR_WAIT(vempty, j & 1);
            MBAR_EXPECT(vfull, 32768u);
            int cy = grow_k + (j + 1) * 64;
            TMA2D(ab + SVH,        &mVh, 0,  cy, vfull);
            TMA2D(ab + SVH + 8192, &mVh, 64, cy, vfull);
            TMA2D(ab + SVL,        &mVl, 0,  cy, vfull);
            TMA2D(ab + SVL + 8192, &mVl, 64, cy, vfull);
        }
    }

    // epilogue: y (B,T,C) split bf16
    float inv0 = 1.0f / l0r, inv1 = 1.0f / l1r;
    int b = bh >> 4, h = bh & 15;
    int t0 = qtile * 64 + wid * 16 + (lane >> 2);
    size_t base0 = (size_t)(b * TT + t0) * CC + h * HD;
    size_t base1 = base0 + (size_t)8 * CC;
    int c0 = (lane & 3) << 1;
#pragma unroll
    for (int ng = 0; ng < 16; ng++) {
        int col = ng * 8 + c0;
        float e0 = o[ng][0] * inv0, e1 = o[ng][1] * inv0;
        float f0 = o[ng][2] * inv1, f1 = o[ng][3] * inv1;
        *(uint32_t*)((char*)yh + (base0 + col) * 2) = packbf(e0, e1);
        *(uint32_t*)((char*)yl + (base0 + col) * 2) =
            packbf(e0 - bfval(e0), e1 - bfval(e1));
        *(uint32_t*)((char*)yh + (base1 + col) * 2) = packbf(f0, f1);
        *(uint32_t*)((char*)yl + (base1 + col) * 2) =
            packbf(f0 - bfval(f0), f1 - bfval(f1));
    }
}

// ---------------- host: tensormap encode via driver entry point ------------------
typedef CUresult (*EncodeFn)(CUtensorMap*, CUtensorMapDataType, cuuint32_t, void*,
                             const cuuint64_t*, const cuuint64_t*, const cuuint32_t*,
                             const cuuint32_t*, CUtensorMapInterleave, CUtensorMapSwizzle,
                             CUtensorMapL2promotion, CUtensorMapFloatOOBfill);

static void mk_map(EncodeFn enc, CUtensorMap* m, void* base, uint64_t cols,
                   uint64_t rows, uint32_t boxRows) {
    cuuint64_t dims[2] = {(cuuint64_t)cols, (cuuint64_t)rows};
    cuuint64_t strides[1] = {(cuuint64_t)cols * 2};
    cuuint32_t box[2] = {64u, boxRows};
    cuuint32_t es[2] = {1u, 1u};
    enc(m, CU_TENSOR_MAP_DATA_TYPE_BFLOAT16, 2, base, dims, strides, box, es,
        CU_TENSOR_MAP_INTERLEAVE_NONE, CU_TENSOR_MAP_SWIZZLE_128B,
        CU_TENSOR_MAP_L2_PROMOTION_L2_128B, CU_TENSOR_MAP_FLOAT_OOB_FILL_NONE);
}

// ---------------- launch --------------------------------------------------------
extern "C" void kernel_launch(void* const* d_in, const int* in_sizes, int n_in,
                              void* d_out, int out_size) {
    const float* x  = (const float*)d_in[0];
    const float* Wq = (const float*)d_in[1];
    const float* Wk = (const float*)d_in[2];
    const float* Wv = (const float*)d_in[3];
    const float* Wp = (const float*)d_in[4];
    float* out = (float*)d_out;

    __nv_bfloat16 *xh, *xl, *yh, *yl, *wh, *wl;
    __nv_bfloat16 *qh, *ql, *kh, *kl, *vh, *vl;
    cudaGetSymbolAddress((void**)&xh, g_xh);
    cudaGetSymbolAddress((void**)&xl, g_xl);
    cudaGetSymbolAddress((void**)&yh, g_yh);
    cudaGetSymbolAddress((void**)&yl, g_yl);
    cudaGetSymbolAddress((void**)&wh, g_wh);
    cudaGetSymbolAddress((void**)&wl, g_wl);
    cudaGetSymbolAddress((void**)&qh, g_qh);
    cudaGetSymbolAddress((void**)&ql, g_ql);
    cudaGetSymbolAddress((void**)&kh, g_kh);
    cudaGetSymbolAddress((void**)&kl, g_kl);
    cudaGetSymbolAddress((void**)&vh, g_vh);
    cudaGetSymbolAddress((void**)&vl, g_vl);

    void* fn = nullptr;
    cudaDriverEntryPointQueryResult st;
    cudaGetDriverEntryPoint("cuTensorMapEncodeTiled", &fn, cudaEnableDefault, &st);
    EncodeFn enc = (EncodeFn)fn;
    const uint64_t QR = (uint64_t)BSZ * NH * TT;
    CUtensorMap mXh, mXl, mYh, mYl, mWh[4], mWl[4];
    CUtensorMap mQh, mQl, mKh, mKl, mVh, mVl;
    mk_map(enc, &mXh, xh, CC, MM, BM);
    mk_map(enc, &mXl, xl, CC, MM, BM);
    mk_map(enc, &mYh, yh, CC, MM, BM);
    mk_map(enc, &mYl, yl, CC, MM, BM);
    for (int i = 0; i < 4; i++) {
        mk_map(enc, &mWh[i], wh + (size_t)i * CC * CC, CC, CC, BN);
        mk_map(enc, &mWl[i], wl + (size_t)i * CC * CC, CC, CC, BN);
    }
    mk_map(enc, &mQh, qh, HD, QR, 64);
    mk_map(enc, &mQl, ql, HD, QR, 64);
    mk_map(enc, &mKh, kh, HD, QR, 64);
    mk_map(enc, &mKl, kl, HD, QR, 64);
    mk_map(enc, &mVh, vh, HD, QR, 64);
    mk_map(enc, &mVl, vl, HD, QR, 64);

    rope_table_kernel<<<(TT * (HD/2) + 255) / 256, 256>>>();

    const int NX4 = MM * CC / 4;
    const int NW4 = CC * CC / 4;
    cvt_split_kernel<<<(NX4 + 255) / 256, 256>>>(x, xh, xl, NX4);
    const float* Ws[4] = {Wq, Wk, Wv, Wp};
    for (int i = 0; i < 4; i++)
        cvt_split_kernel<<<(NW4 + 255) / 256, 256>>>(Ws[i], wh + (size_t)i * CC * CC,
                                                     wl + (size_t)i * CC * CC, NW4);

    cudaFuncSetAttribute(gemm_tma<0>, cudaFuncAttributeMaxDynamicSharedMemorySize, GEMM_SMEM);
    cudaFuncSetAttribute(gemm_tma<1>, cudaFuncAttributeMaxDynamicSharedMemorySize, GEMM_SMEM);
    cudaFuncSetAttribute(gemm_tma<2>, cudaFuncAttributeMaxDynamicSharedMemorySize, GEMM_SMEM);
    cudaFuncSetAttribute(attn_tc, cudaFuncAttributeMaxDynamicSharedMemorySize, ATTN_SMEM);

    dim3 gg(CC / BN, MM / BM);     // (8, 64)
    gemm_tma<1><<<gg, 256, GEMM_SMEM>>>(mXh, mXl, mWh[0], mWl[0], out, qh, ql);
    gemm_tma<1><<<gg, 256, GEMM_SMEM>>>(mXh, mXl, mWh[1], mWl[1], out, kh, kl);
    gemm_tma<2><<<gg, 256, GEMM_SMEM>>>(mXh, mXl, mWh[2], mWl[2], out, vh, vl);

    attn_tc<<<dim3(TT / 64, BSZ * NH), 128, ATTN_SMEM>>>(mQh, mQl, mKh, mKl,
                                                         mVh, mVl, yh, yl);

    gemm_tma<0><<<gg, 256, GEMM_SMEM>>>(mYh, mYl, mWh[3], mWl[3], out, qh, ql);
}

// round 6
// speedup vs baseline: 4.5626x; 1.3818x over previous
#include <cuda_runtime.h>
#include <cuda.h>
#include <cuda_fp16.h>
#include <math.h>
#include <cstdint>

#define BSZ 4
#define TT 2048
#define CC 2048
#define NH 16
#define HD 128
#define MM (BSZ*TT)   // 8192

// ---------------- scratch (device globals: no allocation allowed) -------------
__device__ float g_cos[TT*(HD/2)];
__device__ float g_sin[TT*(HD/2)];
// f16 operand buffers (1KB aligned for TMA)
__device__ __align__(1024) __half g_xh[(size_t)MM*CC];
__device__ __align__(1024) __half g_yh[(size_t)MM*CC];
__device__ __align__(1024) __half g_wh[4][(size_t)CC*CC];
__device__ __align__(1024) __half g_wl[4][(size_t)CC*CC];
__device__ __align__(1024) __half g_qh[(size_t)BSZ*NH*TT*HD];
__device__ __align__(1024) __half g_ql[(size_t)BSZ*NH*TT*HD];
__device__ __align__(1024) __half g_kh[(size_t)BSZ*NH*TT*HD];
__device__ __align__(1024) __half g_kl[(size_t)BSZ*NH*TT*HD];
__device__ __align__(1024) __half g_vh[(size_t)BSZ*NH*TT*HD];
__device__ __align__(1024) __half g_vl[(size_t)BSZ*NH*TT*HD];

// ---------------- PTX helpers --------------------------------------------------
__device__ __forceinline__ uint32_t smem_u32(const void* p) {
    uint32_t a;
    asm("{ .reg .u64 t; cvta.to.shared.u64 t, %1; cvt.u32.u64 %0, t; }" : "=r"(a) : "l"(p));
    return a;
}
#define MBAR_INIT(a, n) asm volatile("mbarrier.init.shared.b64 [%0], %1;" :: "r"(a), "r"(n) : "memory")
#define MBAR_ARRIVE(a)  asm volatile("mbarrier.arrive.shared.b64 _, [%0];" :: "r"(a) : "memory")
#define MBAR_EXPECT(a, tx) asm volatile("mbarrier.arrive.expect_tx.shared.b64 _, [%0], %1;" :: "r"(a), "r"(tx) : "memory")
#define MBAR_WAIT(a, ph) do {                                                      \
    uint32_t _m = (a), _p = (ph), _d;                                              \
    asm volatile("{\n\t.reg .pred p;\n\t"                                          \
        "mbarrier.try_wait.parity.acquire.cta.shared::cta.b64 p, [%1], %2;\n\t"    \
        "selp.b32 %0, 1, 0, p;\n\t}" : "=r"(_d) : "r"(_m), "r"(_p) : "memory");    \
    if (!_d) {                                                                     \
        asm volatile("{\n\t.reg .pred P1;\n\t"                                     \
            "WL_%=:\n\t"                                                           \
            "mbarrier.try_wait.parity.acquire.cta.shared::cta.b64 P1, [%0], %1, 0x989680;\n\t" \
            "@P1 bra.uni WD_%=;\n\tbra.uni WL_%=;\n\tWD_%=:\n\t}"                  \
            :: "r"(_m), "r"(_p) : "memory");                                       \
    }                                                                              \
} while (0)
#define TMA2D(dst, map, cx, cy, mb) \
    asm volatile("cp.async.bulk.tensor.2d.shared::cta.global.tile.mbarrier::complete_tx::bytes " \
        "[%0], [%1, {%2, %3}], [%4];" \
        :: "r"(dst), "l"(map), "r"(cx), "r"(cy), "r"(mb) : "memory")

__device__ __forceinline__ void ldmx4(uint32_t* r, uint32_t addr) {
    asm volatile("ldmatrix.sync.aligned.m8n8.x4.shared.b16 {%0,%1,%2,%3}, [%4];"
                 : "=r"(r[0]), "=r"(r[1]), "=r"(r[2]), "=r"(r[3]) : "r"(addr));
}
__device__ __forceinline__ void ldmx4t(uint32_t* r, uint32_t addr) {
    asm volatile("ldmatrix.sync.aligned.m8n8.x4.trans.shared.b16 {%0,%1,%2,%3}, [%4];"
                 : "=r"(r[0]), "=r"(r[1]), "=r"(r[2]), "=r"(r[3]) : "r"(addr));
}
__device__ __forceinline__ void mmaf16(float* d, const uint32_t* a,
                                       uint32_t b0, uint32_t b1) {
    asm volatile("mma.sync.aligned.m16n8k16.row.col.f32.f16.f16.f32 "
                 "{%0,%1,%2,%3}, {%4,%5,%6,%7}, {%8,%9}, {%0,%1,%2,%3};"
                 : "+f"(d[0]), "+f"(d[1]), "+f"(d[2]), "+f"(d[3])
                 : "r"(a[0]), "r"(a[1]), "r"(a[2]), "r"(a[3]), "r"(b0), "r"(b1));
}
// pack two floats -> f16x2 {lo, hi}
__device__ __forceinline__ uint32_t packf16(float lo, float hi) {
    uint32_t r;
    asm("cvt.rn.f16x2.f32 %0, %1, %2;" : "=r"(r) : "f"(hi), "f"(lo));
    return r;
}
__device__ __forceinline__ float f16val(float x) {
    return __half2float(__float2half(x));
}
// swizzled byte offset within a [rows][128B] k-major tile (== TMA SW128 layout)
__device__ __forceinline__ uint32_t swzoff(int r, int chunk) {
    return (uint32_t)(r * 128 + ((chunk ^ (r & 7)) << 4));
}

// ---------------- RoPE cos/sin table -------------------------------------------
__global__ void rope_table_kernel() {
    int idx = blockIdx.x * blockDim.x + threadIdx.x;
    if (idx >= TT * (HD/2)) return;
    int t = idx / (HD/2);
    int i = idx % (HD/2);
    float inv = (float)pow(10000.0, -(double)(2*i) / (double)HD);
    float ang = (float)t * inv;
    g_cos[idx] = cosf(ang);
    g_sin[idx] = sinf(ang);
}

// ---------------- fp32 -> f16 (hi only) -----------------------------------------
__global__ void cvt_hi_kernel(const float* __restrict__ in,
                              __half* __restrict__ hi, int n4) {
    int i = blockIdx.x * blockDim.x + threadIdx.x;
    if (i >= n4) return;
    float4 v = ((const float4*)in)[i];
    uint2 o;
    o.x = packf16(v.x, v.y);
    o.y = packf16(v.z, v.w);
    ((uint2*)hi)[i] = o;
}

// ---------------- fp32 -> (f16 hi, f16 lo) split ---------------------------------
__global__ void cvt_split_kernel(const float* __restrict__ in,
                                 __half* __restrict__ hi,
                                 __half* __restrict__ lo, int n4) {
    int i = blockIdx.x * blockDim.x + threadIdx.x;
    if (i >= n4) return;
    float4 v = ((const float4*)in)[i];
    uint2 h, l;
    h.x = packf16(v.x, v.y);
    h.y = packf16(v.z, v.w);
    l.x = packf16(v.x - f16val(v.x), v.y - f16val(v.y));
    l.y = packf16(v.z - f16val(v.z), v.w - f16val(v.w));
    ((uint2*)hi)[i] = h;
    ((uint2*)lo)[i] = l;
}

// ---------------- f16 2-pass GEMM via TMA + mma.sync -----------------------------
// CTA 128x256, BK=64, 2-stage TMA pipeline, 8 warps (2m x 4n), warp tile 64x64.
// Passes: Ah*Bh + Ah*Bl (A f16-hi only, B split f16).
#define BM 128
#define BN 256
#define BK 64
#define NKIT (CC / BK)     // 32
#define A_OFF 0
#define BH_OFF 16384
#define BL_OFF 49152
#define STG_SZ 81920
#define GEMM_SMEM (2048 + 2*STG_SZ)

// shared mainloop body as a macro-free inline: implemented twice (qkv / out)

__global__ __launch_bounds__(256, 1)
void gemm_qkv(const __grid_constant__ CUtensorMap tmA,
              const __grid_constant__ CUtensorMap tmB0h,
              const __grid_constant__ CUtensorMap tmB0l,
              const __grid_constant__ CUtensorMap tmB1h,
              const __grid_constant__ CUtensorMap tmB1l,
              const __grid_constant__ CUtensorMap tmB2h,
              const __grid_constant__ CUtensorMap tmB2l,
              __half* __restrict__ qh, __half* __restrict__ ql,
              __half* __restrict__ kh, __half* __restrict__ kl,
              __half* __restrict__ vh, __half* __restrict__ vl) {
    extern __shared__ char smraw[];
    const uint32_t raw = smem_u32(smraw);
    const uint32_t ab = (raw + 64 + 1023) & ~1023u;
    const uint32_t fullb = raw;
    const uint32_t emptyb = raw + 16;
    const int tid = threadIdx.x;
    const int wid = tid >> 5, lane = tid & 31;
    const int wm = wid & 1;
    const int wn = wid >> 1;
    const int m0 = blockIdx.y * BM;
    const int n0 = blockIdx.x * BN;
    const int z = blockIdx.z;
    const CUtensorMap* pbh = (z == 0) ? &tmB0h : (z == 1) ? &tmB1h : &tmB2h;
    const CUtensorMap* pbl = (z == 0) ? &tmB0l : (z == 1) ? &tmB1l : &tmB2l;
    __half* outH = (z == 0) ? qh : (z == 1) ? kh : vh;
    __half* outL = (z == 0) ? ql : (z == 1) ? kl : vl;
    const bool rope = (z < 2);

    if (tid == 0) {
        MBAR_INIT(fullb, 1);     MBAR_INIT(fullb + 8, 1);
        MBAR_INIT(emptyb, 256);  MBAR_INIT(emptyb + 8, 256);
        asm volatile("fence.proxy.async.shared::cta;" ::: "memory");
    }
    __syncthreads();

    float acc[4][8][4];
#pragma unroll
    for (int i = 0; i < 4; i++)
#pragma unroll
        for (int j = 0; j < 8; j++)
#pragma unroll
            for (int q = 0; q < 4; q++) acc[i][j][q] = 0.f;

    const int a_row = wm * 64 + (lane & 15);
    const int a_csel = lane >> 4;
    const int b_row = wn * 64 + ((lane >> 4) << 3) + (lane & 7);
    const int b_csel = (lane >> 3) & 1;

    auto issue = [&](int n) {
        int s = n & 1;
        uint32_t sb = ab + s * STG_SZ;
        uint32_t mb = fullb + s * 8;
        MBAR_EXPECT(mb, (uint32_t)STG_SZ);
        int cx = n * BK;
        TMA2D(sb + A_OFF,  &tmA, cx, m0, mb);
        TMA2D(sb + BH_OFF, pbh,  cx, n0, mb);
        TMA2D(sb + BL_OFF, pbl,  cx, n0, mb);
    };
    if (tid == 0) issue(0);

    for (int c = 0; c < NKIT; ++c) {
        int s = c & 1;
        if (tid == 0 && c + 1 < NKIT) {
            int n = c + 1;
            if (n >= 2) MBAR_WAIT(emptyb + (n & 1) * 8, ((n >> 1) - 1) & 1);
            issue(n);
        }
        MBAR_WAIT(fullb + s * 8, (c >> 1) & 1);

        uint32_t sb = ab + s * STG_SZ;
#pragma unroll
        for (int ks = 0; ks < 4; ks++) {
            uint32_t a4[4][4], bh4[4][4], bl4[4][4];
#pragma unroll
            for (int f = 0; f < 4; f++)
                ldmx4(a4[f], sb + A_OFF + swzoff(a_row + f * 16, 2 * ks + a_csel));
#pragma unroll
            for (int p = 0; p < 4; p++) {
                uint32_t off = swzoff(b_row + p * 16, 2 * ks + b_csel);
                ldmx4(bh4[p], sb + BH_OFF + off);
                ldmx4(bl4[p], sb + BL_OFF + off);
            }
#pragma unroll
            for (int mf = 0; mf < 4; mf++)
#pragma unroll
                for (int nf = 0; nf < 8; nf++) {
                    int p = nf >> 1;
                    int e = (nf & 1) << 1;
                    mmaf16(acc[mf][nf], a4[mf], bh4[p][e], bh4[p][e + 1]);
                    mmaf16(acc[mf][nf], a4[mf], bl4[p][e], bl4[p][e + 1]);
                }
        }
        MBAR_ARRIVE(emptyb + s * 8);
    }

    const int tr = lane >> 2;
    const int tc = (lane & 3) << 1;
#pragma unroll
    for (int mf = 0; mf < 4; mf++) {
#pragma unroll
        for (int nf = 0; nf < 8; nf++) {
            int mA = m0 + wm * 64 + mf * 16 + tr;
            int n  = n0 + wn * 64 + nf * 8 + tc;
            float* d = acc[mf][nf];
#pragma unroll
            for (int half2i = 0; half2i < 2; half2i++) {
                int m = mA + half2i * 8;
                float e = d[half2i * 2], o = d[half2i * 2 + 1];
                int b = m >> 11;
                int t = m & (TT - 1);
                int h = n >> 7;
                int dd = n & (HD - 1);
                size_t dst = ((size_t)(b * NH + h) * TT + t) * HD + dd;
                float e2 = e, o2 = o;
                if (rope) {
                    float cv = g_cos[t * (HD/2) + (dd >> 1)];
                    float sv = g_sin[t * (HD/2) + (dd >> 1)];
                    e2 = e * cv - o * sv;
                    o2 = o * cv + e * sv;
                }
                *(uint32_t*)((char*)outH + dst * 2) = packf16(e2, o2);
                *(uint32_t*)((char*)outL + dst * 2) =
                    packf16(e2 - f16val(e2), o2 - f16val(o2));
            }
        }
    }
}

__global__ __launch_bounds__(256, 1)
void gemm_out(const __grid_constant__ CUtensorMap tmA,
              const __grid_constant__ CUtensorMap tmBh,
              const __grid_constant__ CUtensorMap tmBl,
              float* __restrict__ out) {
    extern __shared__ char smraw[];
    const uint32_t raw = smem_u32(smraw);
    const uint32_t ab = (raw + 64 + 1023) & ~1023u;
    const uint32_t fullb = raw;
    const uint32_t emptyb = raw + 16;
    const int tid = threadIdx.x;
    const int wid = tid >> 5, lane = tid & 31;
    const int wm = wid & 1;
    const int wn = wid >> 1;
    const int m0 = blockIdx.y * BM;
    const int n0 = blockIdx.x * BN;

    if (tid == 0) {
        MBAR_INIT(fullb, 1);     MBAR_INIT(fullb + 8, 1);
        MBAR_INIT(emptyb, 256);  MBAR_INIT(emptyb + 8, 256);
        asm volatile("fence.proxy.async.shared::cta;" ::: "memory");
    }
    __syncthreads();

    float acc[4][8][4];
#pragma unroll
    for (int i = 0; i < 4; i++)
#pragma unroll
        for (int j = 0; j < 8; j++)
#pragma unroll
            for (int q = 0; q < 4; q++) acc[i][j][q] = 0.f;

    const int a_row = wm * 64 + (lane & 15);
    const int a_csel = lane >> 4;
    const int b_row = wn * 64 + ((lane >> 4) << 3) + (lane & 7);
    const int b_csel = (lane >> 3) & 1;

    auto issue = [&](int n) {
        int s = n & 1;
        uint32_t sb = ab + s * STG_SZ;
        uint32_t mb = fullb + s * 8;
        MBAR_EXPECT(mb, (uint32_t)STG_SZ);
        int cx = n * BK;
        TMA2D(sb + A_OFF,  &tmA, cx, m0, mb);
        TMA2D(sb + BH_OFF, &tmBh, cx, n0, mb);
        TMA2D(sb + BL_OFF, &tmBl, cx, n0, mb);
    };
    if (tid == 0) issue(0);

    for (int c = 0; c < NKIT; ++c) {
        int s = c & 1;
        if (tid == 0 && c + 1 < NKIT) {
            int n = c + 1;
            if (n >= 2) MBAR_WAIT(emptyb + (n & 1) * 8, ((n >> 1) - 1) & 1);
            issue(n);
        }
        MBAR_WAIT(fullb + s * 8, (c >> 1) & 1);

        uint32_t sb = ab + s * STG_SZ;
#pragma unroll
        for (int ks = 0; ks < 4; ks++) {
            uint32_t a4[4][4], bh4[4][4], bl4[4][4];
#pragma unroll
            for (int f = 0; f < 4; f++)
                ldmx4(a4[f], sb + A_OFF + swzoff(a_row + f * 16, 2 * ks + a_csel));
#pragma unroll
            for (int p = 0; p < 4; p++) {
                uint32_t off = swzoff(b_row + p * 16, 2 * ks + b_csel);
                ldmx4(bh4[p], sb + BH_OFF + off);
                ldmx4(bl4[p], sb + BL_OFF + off);
            }
#pragma unroll
            for (int mf = 0; mf < 4; mf++)
#pragma unroll
                for (int nf = 0; nf < 8; nf++) {
                    int p = nf >> 1;
                    int e = (nf & 1) << 1;
                    mmaf16(acc[mf][nf], a4[mf], bh4[p][e], bh4[p][e + 1]);
                    mmaf16(acc[mf][nf], a4[mf], bl4[p][e], bl4[p][e + 1]);
                }
        }
        MBAR_ARRIVE(emptyb + s * 8);
    }

    const int tr = lane >> 2;
    const int tc = (lane & 3) << 1;
#pragma unroll
    for (int mf = 0; mf < 4; mf++) {
#pragma unroll
        for (int nf = 0; nf < 8; nf++) {
            int mA = m0 + wm * 64 + mf * 16 + tr;
            int n  = n0 + wn * 64 + nf * 8 + tc;
            float* d = acc[mf][nf];
#pragma unroll
            for (int half2i = 0; half2i < 2; half2i++) {
                int m = mA + half2i * 8;
                float2 v2 = {d[half2i * 2], d[half2i * 2 + 1]};
                *(float2*)(out + (size_t)m * CC + n) = v2;
            }
        }
    }
}

// ---------------- tensor-core flash attention (split f16, causal) ----------------
#define SQH 0
#define SQL 16384
#define SKH 32768
#define SKL 49152
#define SVH 65536
#define SVL 81920
#define ATTN_SMEM (1024 + 98304)

__global__ __launch_bounds__(128, 2)
void attn_tc(const __grid_constant__ CUtensorMap mQh,
             const __grid_constant__ CUtensorMap mQl,
             const __grid_constant__ CUtensorMap mKh,
             const __grid_constant__ CUtensorMap mKl,
             const __grid_constant__ CUtensorMap mVh,
             const __grid_constant__ CUtensorMap mVl,
             __half* __restrict__ yh) {
    extern __shared__ char smraw[];
    const uint32_t raw = smem_u32(smraw);
    const uint32_t ab = (raw + 64 + 1023) & ~1023u;
    const uint32_t qfull = raw, kfull = raw + 8, vfull = raw + 16;
    const uint32_t kempty = raw + 24, vempty = raw + 32;
    const int tid = threadIdx.x, wid = tid >> 5, lane = tid & 31;
    const int qtile = gridDim.x - 1 - blockIdx.x;   // big tiles first
    const int bh = blockIdx.y;
    const int nt = qtile + 1;
    const int grow_q = bh * TT + qtile * 64;
    const int grow_k = bh * TT;

    if (tid == 0) {
        MBAR_INIT(qfull, 1); MBAR_INIT(kfull, 1); MBAR_INIT(vfull, 1);
        MBAR_INIT(kempty, 128); MBAR_INIT(vempty, 128);
        asm volatile("fence.proxy.async.shared::cta;" ::: "memory");
    }
    __syncthreads();
    if (tid == 0) {
        MBAR_EXPECT(qfull, 32768u);
        TMA2D(ab + SQH,        &mQh, 0,  grow_q, qfull);
        TMA2D(ab + SQH + 8192, &mQh, 64, grow_q, qfull);
        TMA2D(ab + SQL,        &mQl, 0,  grow_q, qfull);
        TMA2D(ab + SQL + 8192, &mQl, 64, grow_q, qfull);
        MBAR_EXPECT(kfull, 32768u);
        TMA2D(ab + SKH,        &mKh, 0,  grow_k, kfull);
        TMA2D(ab + SKH + 8192, &mKh, 64, grow_k, kfull);
        TMA2D(ab + SKL,        &mKl, 0,  grow_k, kfull);
        TMA2D(ab + SKL + 8192, &mKl, 64, grow_k, kfull);
        MBAR_EXPECT(vfull, 32768u);
        TMA2D(ab + SVH,        &mVh, 0,  grow_k, vfull);
        TMA2D(ab + SVH + 8192, &mVh, 64, grow_k, vfull);
        TMA2D(ab + SVL,        &mVl, 0,  grow_k, vfull);
        TMA2D(ab + SVL + 8192, &mVl, 64, grow_k, vfull);
    }

    float o[16][4];
#pragma unroll
    for (int i = 0; i < 16; i++)
#pragma unroll
        for (int q = 0; q < 4; q++) o[i][q] = 0.f;
    float m0r = -1e30f, m1r = -1e30f, l0r = 0.f, l1r = 0.f;

    const int q_row = wid * 16 + (lane & 15);
    const int q_csel = lane >> 4;
    const int k_rowbase = ((lane >> 4) << 3) + (lane & 7);
    const int k_csel = (lane >> 3) & 1;
    const int v_rowin = (lane & 7) + (((lane >> 3) & 1) << 3);
    const int v_csel = lane >> 4;
    const float scale = 0.08838834764831843f;

    MBAR_WAIT(qfull, 0);

    for (int j = 0; j < nt; j++) {
        MBAR_WAIT(kfull, j & 1);

        float s[8][4];
#pragma unroll
        for (int nf = 0; nf < 8; nf++)
#pragma unroll
            for (int q = 0; q < 4; q++) s[nf][q] = 0.f;

#pragma unroll
        for (int ks = 0; ks < 8; ks++) {
            int half2i = ks >> 2;
            int lc = (ks & 3) << 1;
            uint32_t qh4[4], ql4[4];
            uint32_t qoff = half2i * 8192 + swzoff(q_row, lc + q_csel);
            ldmx4(qh4, ab + SQH + qoff);
            ldmx4(ql4, ab + SQL + qoff);
#pragma unroll
            for (int p = 0; p < 4; p++) {
                uint32_t kh4[4], kl4[4];
                uint32_t koff = half2i * 8192 + swzoff(p * 16 + k_rowbase, lc + k_csel);
                ldmx4(kh4, ab + SKH + koff);
                ldmx4(kl4, ab + SKL + koff);
#pragma unroll
                for (int e2 = 0; e2 < 2; e2++) {
                    int nf = p * 2 + e2;
                    int e = e2 << 1;
                    mmaf16(s[nf], qh4, kh4[e], kh4[e + 1]);
                    mmaf16(s[nf], qh4, kl4[e], kl4[e + 1]);
                    mmaf16(s[nf], ql4, kh4[e], kh4[e + 1]);
                }
            }
        }
        MBAR_ARRIVE(kempty);
        if (tid == 0 && j + 1 < nt) {
            MBAR_WAIT(kempty, j & 1);
            MBAR_EXPECT(kfull, 32768u);
            int cy = grow_k + (j + 1) * 64;
            TMA2D(ab + SKH,        &mKh, 0,  cy, kfull);
            TMA2D(ab + SKH + 8192, &mKh, 64, cy, kfull);
            TMA2D(ab + SKL,        &mKl, 0,  cy, kfull);
            TMA2D(ab + SKL + 8192, &mKl, 64, cy, kfull);
        }

#pragma unroll
        for (int nf = 0; nf < 8; nf++)
#pragma unroll
            for (int q = 0; q < 4; q++) s[nf][q] *= scale;
        if (j == qtile) {
            int r0 = wid * 16 + (lane >> 2);
#pragma unroll
            for (int nf = 0; nf < 8; nf++) {
                int c0 = nf * 8 + ((lane & 3) << 1);
                if (c0     > r0)     s[nf][0] = -1e30f;
                if (c0 + 1 > r0)     s[nf][1] = -1e30f;
                if (c0     > r0 + 8) s[nf][2] = -1e30f;
                if (c0 + 1 > r0 + 8) s[nf][3] = -1e30f;
            }
        }

        float rm0 = -1e30f, rm1 = -1e30f;
#pragma unroll
        for (int nf = 0; nf < 8; nf++) {
            rm0 = fmaxf(rm0, fmaxf(s[nf][0], s[nf][1]));
            rm1 = fmaxf(rm1, fmaxf(s[nf][2], s[nf][3]));
        }
        rm0 = fmaxf(rm0, __shfl_xor_sync(0xffffffffu, rm0, 1));
        rm0 = fmaxf(rm0, __shfl_xor_sync(0xffffffffu, rm0, 2));
        rm1 = fmaxf(rm1, __shfl_xor_sync(0xffffffffu, rm1, 1));
        rm1 = fmaxf(rm1, __shfl_xor_sync(0xffffffffu, rm1, 2));
        float mn0 = fmaxf(m0r, rm0), mn1 = fmaxf(m1r, rm1);
        float al0 = __expf(m0r - mn0), al1 = __expf(m1r - mn1);
        m0r = mn0; m1r = mn1;

        float rs0 = 0.f, rs1 = 0.f;
        uint32_t aph[4][4], apl[4][4];
#pragma unroll
        for (int ks2 = 0; ks2 < 4; ks2++) {
#pragma unroll
            for (int hn = 0; hn < 2; hn++) {
                int nf = 2 * ks2 + hn;
                float p0 = __expf(s[nf][0] - mn0);
                float p1 = __expf(s[nf][1] - mn0);
                float p2 = __expf(s[nf][2] - mn1);
                float p3 = __expf(s[nf][3] - mn1);
                rs0 += p0 + p1; rs1 += p2 + p3;
                aph[ks2][hn * 2]     = packf16(p0, p1);
                aph[ks2][hn * 2 + 1] = packf16(p2, p3);
                apl[ks2][hn * 2]     = packf16(p0 - f16val(p0), p1 - f16val(p1));
                apl[ks2][hn * 2 + 1] = packf16(p2 - f16val(p2), p3 - f16val(p3));
            }
        }
        rs0 += __shfl_xor_sync(0xffffffffu, rs0, 1);
        rs0 += __shfl_xor_sync(0xffffffffu, rs0, 2);
        rs1 += __shfl_xor_sync(0xffffffffu, rs1, 1);
        rs1 += __shfl_xor_sync(0xffffffffu, rs1, 2);
        l0r = l0r * al0 + rs0;
        l1r = l1r * al1 + rs1;

#pragma unroll
        for (int ng = 0; ng < 16; ng++) {
            o[ng][0] *= al0; o[ng][1] *= al0;
            o[ng][2] *= al1; o[ng][3] *= al1;
        }

        MBAR_WAIT(vfull, j & 1);
#pragma unroll
        for (int ks2 = 0; ks2 < 4; ks2++) {
#pragma unroll
            for (int g = 0; g < 8; g++) {
                uint32_t vh4[4], vl4[4];
                int half2i = g >> 2;
                uint32_t voff = half2i * 8192 +
                                swzoff(ks2 * 16 + v_rowin, ((g & 3) << 1) + v_csel);
                ldmx4t(vh4, ab + SVH + voff);
                ldmx4t(vl4, ab + SVL + voff);
#pragma unroll
                for (int e2 = 0; e2 < 2; e2++) {
                    int ng = g * 2 + e2;
                    int e = e2 << 1;
                    mmaf16(o[ng], aph[ks2], vh4[e], vh4[e + 1]);
                    mmaf16(o[ng], aph[ks2], vl4[e], vl4[e + 1]);
                    mmaf16(o[ng], apl[ks2], vh4[e], vh4[e + 1]);
                }
            }
        }
        MBAR_ARRIVE(vempty);
        if (tid == 0 && j + 1 < nt) {
            MBAR_WAIT(vempty, j & 1);
            MBAR_EXPECT(vfull, 32768u);
            int cy = grow_k + (j + 1) * 64;
            TMA2D(ab + SVH,        &mVh, 0,  cy, vfull);
            TMA2D(ab + SVH + 8192, &mVh, 64, cy, vfull);
            TMA2D(ab + SVL,        &mVl, 0,  cy, vfull);
            TMA2D(ab + SVL + 8192, &mVl, 64, cy, vfull);
        }
    }

    // epilogue: y (B,T,C) f16 hi
    float inv0 = 1.0f / l0r, inv1 = 1.0f / l1r;
    int b = bh >> 4, h = bh & 15;
    int t0 = qtile * 64 + wid * 16 + (lane >> 2);
    size_t base0 = (size_t)(b * TT + t0) * CC + h * HD;
    size_t base1 = base0 + (size_t)8 * CC;
    int c0 = (lane & 3) << 1;
#pragma unroll
    for (int ng = 0; ng < 16; ng++) {
        int col = ng * 8 + c0;
        *(uint32_t*)((char*)yh + (base0 + col) * 2) =
            packf16(o[ng][0] * inv0, o[ng][1] * inv0);
        *(uint32_t*)((char*)yh + (base1 + col) * 2) =
            packf16(o[ng][2] * inv1, o[ng][3] * inv1);
    }
}

// ---------------- host: tensormap encode via driver entry point ------------------
typedef CUresult (*EncodeFn)(CUtensorMap*, CUtensorMapDataType, cuuint32_t, void*,
                             const cuuint64_t*, const cuuint64_t*, const cuuint32_t*,
                             const cuuint32_t*, CUtensorMapInterleave, CUtensorMapSwizzle,
                             CUtensorMapL2promotion, CUtensorMapFloatOOBfill);

static void mk_map(EncodeFn enc, CUtensorMap* m, void* base, uint64_t cols,
                   uint64_t rows, uint32_t boxRows) {
    cuuint64_t dims[2] = {(cuuint64_t)cols, (cuuint64_t)rows};
    cuuint64_t strides[1] = {(cuuint64_t)cols * 2};
    cuuint32_t box[2] = {64u, boxRows};
    cuuint32_t es[2] = {1u, 1u};
    enc(m, CU_TENSOR_MAP_DATA_TYPE_FLOAT16, 2, base, dims, strides, box, es,
        CU_TENSOR_MAP_INTERLEAVE_NONE, CU_TENSOR_MAP_SWIZZLE_128B,
        CU_TENSOR_MAP_L2_PROMOTION_L2_128B, CU_TENSOR_MAP_FLOAT_OOB_FILL_NONE);
}

// ---------------- launch --------------------------------------------------------
extern "C" void kernel_launch(void* const* d_in, const int* in_sizes, int n_in,
                              void* d_out, int out_size) {
    const float* x  = (const float*)d_in[0];
    const float* Wq = (const float*)d_in[1];
    const float* Wk = (const float*)d_in[2];
    const float* Wv = (const float*)d_in[3];
    const float* Wp = (const float*)d_in[4];
    float* out = (float*)d_out;

    __half *xh, *yh, *wh, *wl;
    __half *qh, *ql, *kh, *kl, *vh, *vl;
    cudaGetSymbolAddress((void**)&xh, g_xh);
    cudaGetSymbolAddress((void**)&yh, g_yh);
    cudaGetSymbolAddress((void**)&wh, g_wh);
    cudaGetSymbolAddress((void**)&wl, g_wl);
    cudaGetSymbolAddress((void**)&qh, g_qh);
    cudaGetSymbolAddress((void**)&ql, g_ql);
    cudaGetSymbolAddress((void**)&kh, g_kh);
    cudaGetSymbolAddress((void**)&kl, g_kl);
    cudaGetSymbolAddress((void**)&vh, g_vh);
    cudaGetSymbolAddress((void**)&vl, g_vl);

    void* fn = nullptr;
    cudaDriverEntryPointQueryResult st;
    cudaGetDriverEntryPoint("cuTensorMapEncodeTiled", &fn, cudaEnableDefault, &st);
    EncodeFn enc = (EncodeFn)fn;
    const uint64_t QR = (uint64_t)BSZ * NH * TT;
    CUtensorMap mXh, mYh, mWh[4], mWl[4];
    CUtensorMap mQh, mQl, mKh, mKl, mVh, mVl;
    mk_map(enc, &mXh, xh, CC, MM, BM);
    mk_map(enc, &mYh, yh, CC, MM, BM);
    for (int i = 0; i < 4; i++) {
        mk_map(enc, &mWh[i], wh + (size_t)i * CC * CC, CC, CC, BN);
        mk_map(enc, &mWl[i], wl + (size_t)i * CC * CC, CC, CC, BN);
    }
    mk_map(enc, &mQh, qh, HD, QR, 64);
    mk_map(enc, &mQl, ql, HD, QR, 64);
    mk_map(enc, &mKh, kh, HD, QR, 64);
    mk_map(enc, &mKl, kl, HD, QR, 64);
    mk_map(enc, &mVh, vh, HD, QR, 64);
    mk_map(enc, &mVl, vl, HD, QR, 64);

    rope_table_kernel<<<(TT * (HD/2) + 255) / 256, 256>>>();

    const int NX4 = MM * CC / 4;
    const int NW4 = CC * CC / 4;
    cvt_hi_kernel<<<(NX4 + 255) / 256, 256>>>(x, xh, NX4);
    const float* Ws[4] = {Wq, Wk, Wv, Wp};
    for (int i = 0; i < 4; i++)
        cvt_split_kernel<<<(NW4 + 255) / 256, 256>>>(Ws[i], wh + (size_t)i * CC * CC,
                                                     wl + (size_t)i * CC * CC, NW4);

    cudaFuncSetAttribute(gemm_qkv, cudaFuncAttributeMaxDynamicSharedMemorySize, GEMM_SMEM);
    cudaFuncSetAttribute(gemm_out, cudaFuncAttributeMaxDynamicSharedMemorySize, GEMM_SMEM);
    cudaFuncSetAttribute(attn_tc, cudaFuncAttributeMaxDynamicSharedMemorySize, ATTN_SMEM);

    dim3 gq(CC / BN, MM / BM, 3);   // (8, 64, 3)
    gemm_qkv<<<gq, 256, GEMM_SMEM>>>(mXh, mWh[0], mWl[0], mWh[1], mWl[1],
                                     mWh[2], mWl[2], qh, ql, kh, kl, vh, vl);

    attn_tc<<<dim3(TT / 64, BSZ * NH), 128, ATTN_SMEM>>>(mQh, mQl, mKh, mKl,
                                                         mVh, mVl, yh);

    dim3 gg(CC / BN, MM / BM);      // (8, 64)
    gemm_out<<<gg, 256, GEMM_SMEM>>>(mYh, mWh[3], mWl[3], out);
}